// round 1
// baseline (speedup 1.0000x reference)
#include <cuda_runtime.h>
#include <cuda_bf16.h>

// Problem constants
#define B_    4
#define T_    2048
#define C_    768
#define H_    12
#define DH_   64
#define M_    (B_ * T_)      // 8192 rows
#define NQKV_ (3 * C_)       // 2304

// Scratch (allocation-free rule: __device__ globals)
__device__ float g_q[B_ * H_ * T_ * DH_];   // [b,h,t,d]
__device__ float g_k[B_ * H_ * T_ * DH_];
__device__ float g_v[B_ * H_ * T_ * DH_];
__device__ float g_y[M_ * C_];              // attention output, [b,t,c]

// ---------------------------------------------------------------------------
// Kernel 1: qkv = x @ w_attn + b_attn, scattered into q/k/v [b,h,t,d]
// Classic 128x128x8 register-blocked SGEMM, 256 threads, 8x8 per thread.
// ---------------------------------------------------------------------------
__global__ __launch_bounds__(256) void qkv_gemm_kernel(
    const float* __restrict__ X,     // [M_, C_]
    const float* __restrict__ W,     // [C_, NQKV_]
    const float* __restrict__ bias)  // [NQKV_]
{
    const int K  = C_;
    const int Nw = NQKV_;
    __shared__ float As[8][128];
    __shared__ float Bs[8][128];

    const int bn  = blockIdx.x * 128;
    const int bm  = blockIdx.y * 128;
    const int tid = threadIdx.x;

    const int arow = tid >> 1;
    const int acol = (tid & 1) << 2;
    const int brow = tid >> 5;
    const int bcol = (tid & 31) << 2;

    const float* Aptr = X + (size_t)(bm + arow) * K + acol;
    const float* Bptr = W + (size_t)brow * Nw + bn + bcol;

    const int ty = (tid >> 4) << 3;
    const int tx = (tid & 15) << 3;

    float acc[8][8] = {};

    for (int k0 = 0; k0 < K; k0 += 8) {
        float4 a  = *reinterpret_cast<const float4*>(Aptr + k0);
        float4 bv = *reinterpret_cast<const float4*>(Bptr + (size_t)k0 * Nw);
        As[acol + 0][arow] = a.x;
        As[acol + 1][arow] = a.y;
        As[acol + 2][arow] = a.z;
        As[acol + 3][arow] = a.w;
        *reinterpret_cast<float4*>(&Bs[brow][bcol]) = bv;
        __syncthreads();

        #pragma unroll
        for (int k = 0; k < 8; k++) {
            float ar[8], br[8];
            *reinterpret_cast<float4*>(&ar[0]) = *reinterpret_cast<float4*>(&As[k][ty]);
            *reinterpret_cast<float4*>(&ar[4]) = *reinterpret_cast<float4*>(&As[k][ty + 4]);
            *reinterpret_cast<float4*>(&br[0]) = *reinterpret_cast<float4*>(&Bs[k][tx]);
            *reinterpret_cast<float4*>(&br[4]) = *reinterpret_cast<float4*>(&Bs[k][tx + 4]);
            #pragma unroll
            for (int i = 0; i < 8; i++)
                #pragma unroll
                for (int j = 0; j < 8; j++)
                    acc[i][j] = fmaf(ar[i], br[j], acc[i][j]);
        }
        __syncthreads();
    }

    // Epilogue: add bias, scatter into q/k/v [b,h,t,d]
    #pragma unroll
    for (int i = 0; i < 8; i++) {
        const int m  = bm + ty + i;
        const int bb = m >> 11;          // / T_
        const int t  = m & (T_ - 1);
        #pragma unroll
        for (int j = 0; j < 8; j++) {
            const int n = bn + tx + j;
            float v = acc[i][j] + bias[n];
            const int which = n / C_;     // 0=q, 1=k, 2=v
            const int c = n - which * C_;
            const int hh = c >> 6;
            const int d  = c & 63;
            float* dst = (which == 0) ? g_q : (which == 1) ? g_k : g_v;
            dst[((((size_t)bb * H_ + hh) * T_ + t) << 6) + d] = v;
        }
    }
}

// ---------------------------------------------------------------------------
// Kernel 2: causal flash attention, fp32, online softmax.
// Block: one (b,h) and one 64-query tile. 256 threads.
// KV tiles of 32. S tile 64x32, O tile 64x64 in registers (4x4 per thread).
// ---------------------------------------------------------------------------
__global__ __launch_bounds__(256) void attn_kernel()
{
    const int qt = blockIdx.x;   // 0..31
    const int bh = blockIdx.y;   // 0..47
    const int qbase = qt << 6;

    const float* Qg = g_q + (size_t)bh * T_ * DH_;
    const float* Kg = g_k + (size_t)bh * T_ * DH_;
    const float* Vg = g_v + (size_t)bh * T_ * DH_;

    __shared__ float Qst[DH_][64];     // transposed: [d][r]
    __shared__ float Kst[DH_][32];     // transposed: [d][c]
    __shared__ float Vs[32][DH_];      // [k][c]
    __shared__ float Pst[32][65];      // [c][r], padded
    __shared__ float row_m[64], row_l[64], row_c[64];

    const int tid = threadIdx.x;

    // Load Q tile (transposed into smem)
    for (int i = tid; i < 64 * DH_; i += 256) {
        const int r = i >> 6, d = i & 63;
        Qst[d][r] = Qg[(size_t)(qbase + r) * DH_ + d];
    }
    if (tid < 64) { row_m[tid] = -1e30f; row_l[tid] = 0.0f; }

    float acc_o[4][4] = {};
    const int ty = tid >> 4, tx = tid & 15;
    const int r0  = ty << 2;    // 4 query rows per thread
    const int c0s = tx << 1;    // 2 S-columns per thread
    const int c0o = tx << 2;    // 4 O-columns per thread

    const int ntiles = (qbase >> 5) + 2;   // causal: keys 0 .. qbase+63
    __syncthreads();

    for (int kt = 0; kt < ntiles; kt++) {
        const int kvb = kt << 5;

        // Load K (transposed) and V tiles
        for (int i = tid; i < 32 * DH_; i += 256) {
            const int r = i >> 6, d = i & 63;
            Kst[d][r] = Kg[(size_t)(kvb + r) * DH_ + d];
            Vs[r][d]  = Vg[(size_t)(kvb + r) * DH_ + d];
        }
        __syncthreads();

        // S = Q K^T  (4x2 micro-tile per thread)
        float s00 = 0.f, s01 = 0.f, s10 = 0.f, s11 = 0.f;
        float s20 = 0.f, s21 = 0.f, s30 = 0.f, s31 = 0.f;
        #pragma unroll 16
        for (int d = 0; d < DH_; d++) {
            const float k0v = Kst[d][c0s];
            const float k1v = Kst[d][c0s + 1];
            const float q0 = Qst[d][r0];
            const float q1 = Qst[d][r0 + 1];
            const float q2 = Qst[d][r0 + 2];
            const float q3 = Qst[d][r0 + 3];
            s00 = fmaf(q0, k0v, s00); s01 = fmaf(q0, k1v, s01);
            s10 = fmaf(q1, k0v, s10); s11 = fmaf(q1, k1v, s11);
            s20 = fmaf(q2, k0v, s20); s21 = fmaf(q2, k1v, s21);
            s30 = fmaf(q3, k0v, s30); s31 = fmaf(q3, k1v, s31);
        }

        // Scale + causal mask, store to Pst (pre-exp)
        {
            const float sc = 0.125f;  // 1/sqrt(64)
            float sv[4][2] = {{s00, s01}, {s10, s11}, {s20, s21}, {s30, s31}};
            #pragma unroll
            for (int i = 0; i < 4; i++) {
                #pragma unroll
                for (int j = 0; j < 2; j++) {
                    float v = sv[i][j] * sc;
                    if (kvb + c0s + j > qbase + r0 + i) v = -1e30f;
                    Pst[c0s + j][r0 + i] = v;
                }
            }
        }
        __syncthreads();

        // Row statistics + exponentiation (64 threads, one row each)
        if (tid < 64) {
            const int r = tid;
            const float m_old = row_m[r];
            float mx = m_old;
            #pragma unroll
            for (int c = 0; c < 32; c++) mx = fmaxf(mx, Pst[c][r]);
            const float corr = __expf(m_old - mx);
            float sum = 0.0f;
            #pragma unroll
            for (int c = 0; c < 32; c++) {
                const float e = __expf(Pst[c][r] - mx);
                Pst[c][r] = e;
                sum += e;
            }
            row_l[r] = row_l[r] * corr + sum;
            row_m[r] = mx;
            row_c[r] = corr;
        }
        __syncthreads();

        // Rescale O and accumulate O += P @ V (4x4 per thread, inner k=32)
        {
            const float cc0 = row_c[r0], cc1 = row_c[r0 + 1];
            const float cc2 = row_c[r0 + 2], cc3 = row_c[r0 + 3];
            #pragma unroll
            for (int j = 0; j < 4; j++) {
                acc_o[0][j] *= cc0; acc_o[1][j] *= cc1;
                acc_o[2][j] *= cc2; acc_o[3][j] *= cc3;
            }
            #pragma unroll
            for (int k = 0; k < 32; k++) {
                const float p0 = Pst[k][r0];
                const float p1 = Pst[k][r0 + 1];
                const float p2 = Pst[k][r0 + 2];
                const float p3 = Pst[k][r0 + 3];
                const float v0 = Vs[k][c0o];
                const float v1 = Vs[k][c0o + 1];
                const float v2 = Vs[k][c0o + 2];
                const float v3 = Vs[k][c0o + 3];
                acc_o[0][0] = fmaf(p0, v0, acc_o[0][0]);
                acc_o[0][1] = fmaf(p0, v1, acc_o[0][1]);
                acc_o[0][2] = fmaf(p0, v2, acc_o[0][2]);
                acc_o[0][3] = fmaf(p0, v3, acc_o[0][3]);
                acc_o[1][0] = fmaf(p1, v0, acc_o[1][0]);
                acc_o[1][1] = fmaf(p1, v1, acc_o[1][1]);
                acc_o[1][2] = fmaf(p1, v2, acc_o[1][2]);
                acc_o[1][3] = fmaf(p1, v3, acc_o[1][3]);
                acc_o[2][0] = fmaf(p2, v0, acc_o[2][0]);
                acc_o[2][1] = fmaf(p2, v1, acc_o[2][1]);
                acc_o[2][2] = fmaf(p2, v2, acc_o[2][2]);
                acc_o[2][3] = fmaf(p2, v3, acc_o[2][3]);
                acc_o[3][0] = fmaf(p3, v0, acc_o[3][0]);
                acc_o[3][1] = fmaf(p3, v1, acc_o[3][1]);
                acc_o[3][2] = fmaf(p3, v2, acc_o[3][2]);
                acc_o[3][3] = fmaf(p3, v3, acc_o[3][3]);
            }
        }
        __syncthreads();
    }

    // Final normalization and write to g_y [b, t, h*Dh + c]
    const int b = bh / H_;
    const int h = bh - b * H_;
    #pragma unroll
    for (int i = 0; i < 4; i++) {
        const float inv = 1.0f / row_l[r0 + i];
        const int t = qbase + r0 + i;
        float* yrow = g_y + ((size_t)b * T_ + t) * C_ + h * DH_ + c0o;
        #pragma unroll
        for (int j = 0; j < 4; j++)
            yrow[j] = acc_o[i][j] * inv;
    }
}

// ---------------------------------------------------------------------------
// Kernel 3: out = y @ w_proj + b_proj   (M=8192, K=768, N=768)
// ---------------------------------------------------------------------------
__global__ __launch_bounds__(256) void proj_gemm_kernel(
    const float* __restrict__ W,     // [C_, C_]
    const float* __restrict__ bias,  // [C_]
    float* __restrict__ out)         // [M_, C_]
{
    const int K  = C_;
    const int Nw = C_;
    __shared__ float As[8][128];
    __shared__ float Bs[8][128];

    const int bn  = blockIdx.x * 128;
    const int bm  = blockIdx.y * 128;
    const int tid = threadIdx.x;

    const int arow = tid >> 1;
    const int acol = (tid & 1) << 2;
    const int brow = tid >> 5;
    const int bcol = (tid & 31) << 2;

    const float* Aptr = g_y + (size_t)(bm + arow) * K + acol;
    const float* Bptr = W + (size_t)brow * Nw + bn + bcol;

    const int ty = (tid >> 4) << 3;
    const int tx = (tid & 15) << 3;

    float acc[8][8] = {};

    for (int k0 = 0; k0 < K; k0 += 8) {
        float4 a  = *reinterpret_cast<const float4*>(Aptr + k0);
        float4 bv = *reinterpret_cast<const float4*>(Bptr + (size_t)k0 * Nw);
        As[acol + 0][arow] = a.x;
        As[acol + 1][arow] = a.y;
        As[acol + 2][arow] = a.z;
        As[acol + 3][arow] = a.w;
        *reinterpret_cast<float4*>(&Bs[brow][bcol]) = bv;
        __syncthreads();

        #pragma unroll
        for (int k = 0; k < 8; k++) {
            float ar[8], br[8];
            *reinterpret_cast<float4*>(&ar[0]) = *reinterpret_cast<float4*>(&As[k][ty]);
            *reinterpret_cast<float4*>(&ar[4]) = *reinterpret_cast<float4*>(&As[k][ty + 4]);
            *reinterpret_cast<float4*>(&br[0]) = *reinterpret_cast<float4*>(&Bs[k][tx]);
            *reinterpret_cast<float4*>(&br[4]) = *reinterpret_cast<float4*>(&Bs[k][tx + 4]);
            #pragma unroll
            for (int i = 0; i < 8; i++)
                #pragma unroll
                for (int j = 0; j < 8; j++)
                    acc[i][j] = fmaf(ar[i], br[j], acc[i][j]);
        }
        __syncthreads();
    }

    #pragma unroll
    for (int i = 0; i < 8; i++) {
        const int m = bm + ty + i;
        #pragma unroll
        for (int j = 0; j < 8; j++) {
            const int n = bn + tx + j;
            out[(size_t)m * Nw + n] = acc[i][j] + bias[n];
        }
    }
}

// ---------------------------------------------------------------------------
// Launch
// ---------------------------------------------------------------------------
extern "C" void kernel_launch(void* const* d_in, const int* in_sizes, int n_in,
                              void* d_out, int out_size)
{
    const float* x      = (const float*)d_in[0];
    const float* w_attn = (const float*)d_in[1];
    const float* b_attn = (const float*)d_in[2];
    const float* w_proj = (const float*)d_in[3];
    const float* b_proj = (const float*)d_in[4];
    float* out = (float*)d_out;

    dim3 g1(NQKV_ / 128, M_ / 128);   // (18, 64)
    qkv_gemm_kernel<<<g1, 256>>>(x, w_attn, b_attn);

    dim3 g2(T_ / 64, B_ * H_);        // (32, 48)
    attn_kernel<<<g2, 256>>>();

    dim3 g3(C_ / 128, M_ / 128);      // (6, 64)
    proj_gemm_kernel<<<g3, 256>>>(w_proj, b_proj, out);
}

// round 4
// speedup vs baseline: 1.4595x; 1.4595x over previous
#include <cuda_runtime.h>
#include <cuda_bf16.h>
#include <cstdint>

// Problem constants
#define B_    4
#define T_    2048
#define C_    768
#define H_    12
#define DH_   64
#define M_    (B_ * T_)      // 8192 rows
#define NQKV_ (3 * C_)       // 2304

// Scratch (allocation-free rule: __device__ globals)
__device__ float g_q[B_ * H_ * T_ * DH_];   // [b,h,t,d]
__device__ float g_k[B_ * H_ * T_ * DH_];
__device__ float g_v[B_ * H_ * T_ * DH_];
__device__ float g_y[M_ * C_];              // attention output, [b,t,c]

static __device__ __forceinline__ float to_tf32(float x) {
    float r;
    asm("cvt.rna.tf32.f32 %0, %1;" : "=f"(r) : "f"(x));
    return r;
}

static __device__ __forceinline__ void mma_16x8x8(float* c, const uint32_t* a,
                                                  const uint32_t* b) {
    asm volatile(
        "mma.sync.aligned.m16n8k8.row.col.f32.tf32.tf32.f32 "
        "{%0,%1,%2,%3}, {%4,%5,%6,%7}, {%8,%9}, {%0,%1,%2,%3};"
        : "+f"(c[0]), "+f"(c[1]), "+f"(c[2]), "+f"(c[3])
        : "r"(a[0]), "r"(a[1]), "r"(a[2]), "r"(a[3]), "r"(b[0]), "r"(b[1]));
}

// ---------------------------------------------------------------------------
// tf32 mma.sync GEMM: 128x128 block tile, BK=32, 8 warps (2m x 4n), warp
// tile 64x32 (4 m-tiles of 16, 4 n-tiles of 8). Register-prefetch pipeline.
// MODE 0: A = x [M_,C_], W = w_attn [C_,NQKV_]; epilogue scatters to q/k/v
// MODE 1: A = g_y [M_,C_], W = w_proj [C_,C_]; epilogue -> out
// ---------------------------------------------------------------------------
#define BK      32
#define NCHUNK  (C_ / BK)    // 24
#define APITCH  36
#define BPITCH  36

template<int MODE>
__global__ __launch_bounds__(256) void mm_mma_kernel(
    const float* __restrict__ Ain, const float* __restrict__ Wm,
    const float* __restrict__ bias, float* __restrict__ out, int Nw)
{
    __shared__ float As[128][APITCH];   // [m][k]
    __shared__ float Bs[128][BPITCH];   // [n][k]

    const int tid  = threadIdx.x;
    const int wid  = tid >> 5;
    const int lane = tid & 31;
    const int g    = lane >> 2;      // group 0..7
    const int tig  = lane & 3;       // thread-in-group 0..3

    const int bn = blockIdx.x << 7;
    const int bm = blockIdx.y << 7;
    const int wm = (wid >> 2) << 6;  // 0 or 64
    const int wn = (wid & 3) << 5;   // 0,32,64,96

    const float* A = (MODE == 1) ? (const float*)g_y : Ain;

    // A tile loading: 128 rows x 32 cols. 2 threads per row; each thread
    // covers 16 contiguous floats (4 float4s) at col base (tid&1)*16.
    const int ar  = tid >> 1;              // row 0..127
    const int ac0 = (tid & 1) << 4;        // col base 0 or 16
    const float* Abase = A + (size_t)(bm + ar) * C_ + ac0;

    // B tile loading: 32 k-rows x 128 n-cols. Thread handles n = tid&127,
    // k = (tid>>7) + 2p for p = 0..15 (coalesced along n).
    const int bk0 = tid >> 7;              // 0 or 1
    const int bn0 = tid & 127;             // n
    const float* Wbase = Wm + (size_t)bk0 * Nw + bn + bn0;

    float4 ra[4];
    float  rb[16];

    // prefetch chunk 0
    #pragma unroll
    for (int p = 0; p < 4; p++)
        ra[p] = *reinterpret_cast<const float4*>(Abase + (p << 2));
    #pragma unroll
    for (int p = 0; p < 16; p++)
        rb[p] = Wbase[(size_t)(p << 1) * Nw];

    float acc[4][4][4] = {};

    for (int it = 0; it < NCHUNK; ++it) {
        __syncthreads();   // previous compute done; smem reusable

        // store prefetched chunk (cvt to tf32)
        #pragma unroll
        for (int p = 0; p < 4; p++) {
            As[ar][ac0 + (p << 2) + 0] = to_tf32(ra[p].x);
            As[ar][ac0 + (p << 2) + 1] = to_tf32(ra[p].y);
            As[ar][ac0 + (p << 2) + 2] = to_tf32(ra[p].z);
            As[ar][ac0 + (p << 2) + 3] = to_tf32(ra[p].w);
        }
        #pragma unroll
        for (int p = 0; p < 16; p++)
            Bs[bn0][bk0 + (p << 1)] = to_tf32(rb[p]);

        // prefetch next chunk
        if (it + 1 < NCHUNK) {
            const int k0 = (it + 1) << 5;
            #pragma unroll
            for (int p = 0; p < 4; p++)
                ra[p] = *reinterpret_cast<const float4*>(Abase + k0 + (p << 2));
            #pragma unroll
            for (int p = 0; p < 16; p++)
                rb[p] = Wbase[(size_t)(k0 + (p << 1)) * Nw];
        }
        __syncthreads();

        // compute: 4 k-steps of 8
        #pragma unroll
        for (int kk = 0; kk < BK; kk += 8) {
            uint32_t af[4][4], bf[4][2];
            #pragma unroll
            for (int mt = 0; mt < 4; mt++) {
                const int r = wm + (mt << 4) + g;
                af[mt][0] = __float_as_uint(As[r][kk + tig]);
                af[mt][1] = __float_as_uint(As[r + 8][kk + tig]);
                af[mt][2] = __float_as_uint(As[r][kk + tig + 4]);
                af[mt][3] = __float_as_uint(As[r + 8][kk + tig + 4]);
            }
            #pragma unroll
            for (int nt = 0; nt < 4; nt++) {
                const int c = wn + (nt << 3) + g;
                bf[nt][0] = __float_as_uint(Bs[c][kk + tig]);
                bf[nt][1] = __float_as_uint(Bs[c][kk + tig + 4]);
            }
            #pragma unroll
            for (int mt = 0; mt < 4; mt++)
                #pragma unroll
                for (int nt = 0; nt < 4; nt++)
                    mma_16x8x8(acc[mt][nt], af[mt], bf[nt]);
        }
    }

    // Epilogue. c0:(row, col) c1:(row, col+1) c2:(row+8, col) c3:(row+8, col+1)
    // row = wm+16mt+g, col = wn+8nt+2tig
    #pragma unroll
    for (int mt = 0; mt < 4; mt++) {
        #pragma unroll
        for (int half = 0; half < 2; half++) {
            const int row = wm + (mt << 4) + g + (half << 3);
            const int m   = bm + row;
            #pragma unroll
            for (int nt = 0; nt < 4; nt++) {
                const int col = wn + (nt << 3) + (tig << 1);
                const int n   = bn + col;
                float2 v;
                v.x = acc[mt][nt][half ? 2 : 0] + bias[n];
                v.y = acc[mt][nt][half ? 3 : 1] + bias[n + 1];
                if (MODE == 1) {
                    *reinterpret_cast<float2*>(out + (size_t)m * Nw + n) = v;
                } else {
                    const int which = bn / C_;           // tile never straddles q/k/v
                    const int c768  = n - which * C_;
                    const int h  = c768 >> 6;
                    const int d0 = c768 & 63;
                    const int bb = m >> 11;
                    const int t  = m & (T_ - 1);
                    float* dst = ((which == 0) ? g_q : (which == 1) ? g_k : g_v)
                                 + ((((size_t)bb * H_ + h) * T_ + t) << 6) + d0;
                    *reinterpret_cast<float2*>(dst) = v;
                }
            }
        }
    }
}

// ---------------------------------------------------------------------------
// Kernel 2: causal flash attention, fp32, online softmax (unchanged, passing).
// ---------------------------------------------------------------------------
__global__ __launch_bounds__(256) void attn_kernel()
{
    const int qt = blockIdx.x;
    const int bh = blockIdx.y;
    const int qbase = qt << 6;

    const float* Qg = g_q + (size_t)bh * T_ * DH_;
    const float* Kg = g_k + (size_t)bh * T_ * DH_;
    const float* Vg = g_v + (size_t)bh * T_ * DH_;

    __shared__ float Qst[DH_][64];
    __shared__ float Kst[DH_][32];
    __shared__ float Vs[32][DH_];
    __shared__ float Pst[32][65];
    __shared__ float row_m[64], row_l[64], row_c[64];

    const int tid = threadIdx.x;

    for (int i = tid; i < 64 * DH_; i += 256) {
        const int r = i >> 6, d = i & 63;
        Qst[d][r] = Qg[(size_t)(qbase + r) * DH_ + d];
    }
    if (tid < 64) { row_m[tid] = -1e30f; row_l[tid] = 0.0f; }

    float acc_o[4][4] = {};
    const int ty = tid >> 4, tx = tid & 15;
    const int r0  = ty << 2;
    const int c0s = tx << 1;
    const int c0o = tx << 2;

    const int ntiles = (qbase >> 5) + 2;
    __syncthreads();

    for (int kt = 0; kt < ntiles; kt++) {
        const int kvb = kt << 5;

        for (int i = tid; i < 32 * DH_; i += 256) {
            const int r = i >> 6, d = i & 63;
            Kst[d][r] = Kg[(size_t)(kvb + r) * DH_ + d];
            Vs[r][d]  = Vg[(size_t)(kvb + r) * DH_ + d];
        }
        __syncthreads();

        float s00 = 0.f, s01 = 0.f, s10 = 0.f, s11 = 0.f;
        float s20 = 0.f, s21 = 0.f, s30 = 0.f, s31 = 0.f;
        #pragma unroll 16
        for (int d = 0; d < DH_; d++) {
            const float k0v = Kst[d][c0s];
            const float k1v = Kst[d][c0s + 1];
            const float q0 = Qst[d][r0];
            const float q1 = Qst[d][r0 + 1];
            const float q2 = Qst[d][r0 + 2];
            const float q3 = Qst[d][r0 + 3];
            s00 = fmaf(q0, k0v, s00); s01 = fmaf(q0, k1v, s01);
            s10 = fmaf(q1, k0v, s10); s11 = fmaf(q1, k1v, s11);
            s20 = fmaf(q2, k0v, s20); s21 = fmaf(q2, k1v, s21);
            s30 = fmaf(q3, k0v, s30); s31 = fmaf(q3, k1v, s31);
        }

        {
            const float sc = 0.125f;
            float sv[4][2] = {{s00, s01}, {s10, s11}, {s20, s21}, {s30, s31}};
            #pragma unroll
            for (int i = 0; i < 4; i++) {
                #pragma unroll
                for (int j = 0; j < 2; j++) {
                    float v = sv[i][j] * sc;
                    if (kvb + c0s + j > qbase + r0 + i) v = -1e30f;
                    Pst[c0s + j][r0 + i] = v;
                }
            }
        }
        __syncthreads();

        if (tid < 64) {
            const int r = tid;
            const float m_old = row_m[r];
            float mx = m_old;
            #pragma unroll
            for (int c = 0; c < 32; c++) mx = fmaxf(mx, Pst[c][r]);
            const float corr = __expf(m_old - mx);
            float sum = 0.0f;
            #pragma unroll
            for (int c = 0; c < 32; c++) {
                const float e = __expf(Pst[c][r] - mx);
                Pst[c][r] = e;
                sum += e;
            }
            row_l[r] = row_l[r] * corr + sum;
            row_m[r] = mx;
            row_c[r] = corr;
        }
        __syncthreads();

        {
            const float cc0 = row_c[r0], cc1 = row_c[r0 + 1];
            const float cc2 = row_c[r0 + 2], cc3 = row_c[r0 + 3];
            #pragma unroll
            for (int j = 0; j < 4; j++) {
                acc_o[0][j] *= cc0; acc_o[1][j] *= cc1;
                acc_o[2][j] *= cc2; acc_o[3][j] *= cc3;
            }
            #pragma unroll
            for (int k = 0; k < 32; k++) {
                const float p0 = Pst[k][r0];
                const float p1 = Pst[k][r0 + 1];
                const float p2 = Pst[k][r0 + 2];
                const float p3 = Pst[k][r0 + 3];
                const float v0 = Vs[k][c0o];
                const float v1 = Vs[k][c0o + 1];
                const float v2 = Vs[k][c0o + 2];
                const float v3 = Vs[k][c0o + 3];
                acc_o[0][0] = fmaf(p0, v0, acc_o[0][0]);
                acc_o[0][1] = fmaf(p0, v1, acc_o[0][1]);
                acc_o[0][2] = fmaf(p0, v2, acc_o[0][2]);
                acc_o[0][3] = fmaf(p0, v3, acc_o[0][3]);
                acc_o[1][0] = fmaf(p1, v0, acc_o[1][0]);
                acc_o[1][1] = fmaf(p1, v1, acc_o[1][1]);
                acc_o[1][2] = fmaf(p1, v2, acc_o[1][2]);
                acc_o[1][3] = fmaf(p1, v3, acc_o[1][3]);
                acc_o[2][0] = fmaf(p2, v0, acc_o[2][0]);
                acc_o[2][1] = fmaf(p2, v1, acc_o[2][1]);
                acc_o[2][2] = fmaf(p2, v2, acc_o[2][2]);
                acc_o[2][3] = fmaf(p2, v3, acc_o[2][3]);
                acc_o[3][0] = fmaf(p3, v0, acc_o[3][0]);
                acc_o[3][1] = fmaf(p3, v1, acc_o[3][1]);
                acc_o[3][2] = fmaf(p3, v2, acc_o[3][2]);
                acc_o[3][3] = fmaf(p3, v3, acc_o[3][3]);
            }
        }
        __syncthreads();
    }

    const int b = bh / H_;
    const int h = bh - b * H_;
    #pragma unroll
    for (int i = 0; i < 4; i++) {
        const float inv = 1.0f / row_l[r0 + i];
        const int t = qbase + r0 + i;
        float* yrow = g_y + ((size_t)b * T_ + t) * C_ + h * DH_ + c0o;
        #pragma unroll
        for (int j = 0; j < 4; j++)
            yrow[j] = acc_o[i][j] * inv;
    }
}

// ---------------------------------------------------------------------------
// Launch
// ---------------------------------------------------------------------------
extern "C" void kernel_launch(void* const* d_in, const int* in_sizes, int n_in,
                              void* d_out, int out_size)
{
    const float* x      = (const float*)d_in[0];
    const float* w_attn = (const float*)d_in[1];
    const float* b_attn = (const float*)d_in[2];
    const float* w_proj = (const float*)d_in[3];
    const float* b_proj = (const float*)d_in[4];
    float* out = (float*)d_out;

    dim3 g1(NQKV_ / 128, M_ / 128);   // (18, 64)
    mm_mma_kernel<0><<<g1, 256>>>(x, w_attn, b_attn, nullptr, NQKV_);

    dim3 g2(T_ / 64, B_ * H_);        // (32, 48)
    attn_kernel<<<g2, 256>>>();

    dim3 g3(C_ / 128, M_ / 128);      // (6, 64)
    mm_mma_kernel<1><<<g3, 256>>>(nullptr, w_proj, b_proj, out, C_);
}

// round 5
// speedup vs baseline: 3.1571x; 2.1631x over previous
#include <cuda_runtime.h>
#include <cuda_bf16.h>
#include <cstdint>

// Problem constants
#define B_    4
#define T_    2048
#define C_    768
#define H_    12
#define DH_   64
#define M_    (B_ * T_)      // 8192 rows
#define NQKV_ (3 * C_)       // 2304

// Scratch (allocation-free rule: __device__ globals)
__device__ float g_q[B_ * H_ * T_ * DH_];   // [b,h,t,d]
__device__ float g_k[B_ * H_ * T_ * DH_];
__device__ float g_v[B_ * H_ * T_ * DH_];
__device__ float g_y[M_ * C_];              // attention output, [b,t,c]

static __device__ __forceinline__ float to_tf32(float x) {
    float r;
    asm("cvt.rna.tf32.f32 %0, %1;" : "=f"(r) : "f"(x));
    return r;
}

static __device__ __forceinline__ void mma_16x8x8(float* c, const uint32_t* a,
                                                  const uint32_t* b) {
    asm volatile(
        "mma.sync.aligned.m16n8k8.row.col.f32.tf32.tf32.f32 "
        "{%0,%1,%2,%3}, {%4,%5,%6,%7}, {%8,%9}, {%0,%1,%2,%3};"
        : "+f"(c[0]), "+f"(c[1]), "+f"(c[2]), "+f"(c[3])
        : "r"(a[0]), "r"(a[1]), "r"(a[2]), "r"(a[3]), "r"(b[0]), "r"(b[1]));
}

// Fast exp2 on the FMA pipe (degree-5 minimax on [0,1)); input x <= 0.
static __device__ __forceinline__ float fexp2(float x) {
    x = fmaxf(x, -126.0f);
    float fi = floorf(x);
    float f = x - fi;
    float p = fmaf(f, 0.00187757f, 0.00898934f);
    p = fmaf(f, p, 0.05582995f);
    p = fmaf(f, p, 0.24015361f);
    p = fmaf(f, p, 0.69315308f);
    p = fmaf(f, p, 1.0f);
    return p * __int_as_float(((int)fi + 127) << 23);
}

// ---------------------------------------------------------------------------
// tf32 mma.sync GEMM (unchanged from R4, passing): 128x128 tile, BK=32.
// MODE 0: A = x, W = w_attn; epilogue scatters to q/k/v [b,h,t,d]
// MODE 1: A = g_y, W = w_proj; epilogue -> out
// ---------------------------------------------------------------------------
#define BK      32
#define NCHUNK  (C_ / BK)    // 24
#define APITCH  36
#define BPITCH  36

template<int MODE>
__global__ __launch_bounds__(256) void mm_mma_kernel(
    const float* __restrict__ Ain, const float* __restrict__ Wm,
    const float* __restrict__ bias, float* __restrict__ out, int Nw)
{
    __shared__ float As[128][APITCH];
    __shared__ float Bs[128][BPITCH];

    const int tid  = threadIdx.x;
    const int wid  = tid >> 5;
    const int lane = tid & 31;
    const int g    = lane >> 2;
    const int tig  = lane & 3;

    const int bn = blockIdx.x << 7;
    const int bm = blockIdx.y << 7;
    const int wm = (wid >> 2) << 6;
    const int wn = (wid & 3) << 5;

    const float* A = (MODE == 1) ? (const float*)g_y : Ain;

    const int ar  = tid >> 1;
    const int ac0 = (tid & 1) << 4;
    const float* Abase = A + (size_t)(bm + ar) * C_ + ac0;

    const int bk0 = tid >> 7;
    const int bn0 = tid & 127;
    const float* Wbase = Wm + (size_t)bk0 * Nw + bn + bn0;

    float4 ra[4];
    float  rb[16];

    #pragma unroll
    for (int p = 0; p < 4; p++)
        ra[p] = *reinterpret_cast<const float4*>(Abase + (p << 2));
    #pragma unroll
    for (int p = 0; p < 16; p++)
        rb[p] = Wbase[(size_t)(p << 1) * Nw];

    float acc[4][4][4] = {};

    for (int it = 0; it < NCHUNK; ++it) {
        __syncthreads();

        #pragma unroll
        for (int p = 0; p < 4; p++) {
            As[ar][ac0 + (p << 2) + 0] = to_tf32(ra[p].x);
            As[ar][ac0 + (p << 2) + 1] = to_tf32(ra[p].y);
            As[ar][ac0 + (p << 2) + 2] = to_tf32(ra[p].z);
            As[ar][ac0 + (p << 2) + 3] = to_tf32(ra[p].w);
        }
        #pragma unroll
        for (int p = 0; p < 16; p++)
            Bs[bn0][bk0 + (p << 1)] = to_tf32(rb[p]);

        if (it + 1 < NCHUNK) {
            const int k0 = (it + 1) << 5;
            #pragma unroll
            for (int p = 0; p < 4; p++)
                ra[p] = *reinterpret_cast<const float4*>(Abase + k0 + (p << 2));
            #pragma unroll
            for (int p = 0; p < 16; p++)
                rb[p] = Wbase[(size_t)(k0 + (p << 1)) * Nw];
        }
        __syncthreads();

        #pragma unroll
        for (int kk = 0; kk < BK; kk += 8) {
            uint32_t af[4][4], bf[4][2];
            #pragma unroll
            for (int mt = 0; mt < 4; mt++) {
                const int r = wm + (mt << 4) + g;
                af[mt][0] = __float_as_uint(As[r][kk + tig]);
                af[mt][1] = __float_as_uint(As[r + 8][kk + tig]);
                af[mt][2] = __float_as_uint(As[r][kk + tig + 4]);
                af[mt][3] = __float_as_uint(As[r + 8][kk + tig + 4]);
            }
            #pragma unroll
            for (int nt = 0; nt < 4; nt++) {
                const int c = wn + (nt << 3) + g;
                bf[nt][0] = __float_as_uint(Bs[c][kk + tig]);
                bf[nt][1] = __float_as_uint(Bs[c][kk + tig + 4]);
            }
            #pragma unroll
            for (int mt = 0; mt < 4; mt++)
                #pragma unroll
                for (int nt = 0; nt < 4; nt++)
                    mma_16x8x8(acc[mt][nt], af[mt], bf[nt]);
        }
    }

    #pragma unroll
    for (int mt = 0; mt < 4; mt++) {
        #pragma unroll
        for (int half = 0; half < 2; half++) {
            const int row = wm + (mt << 4) + g + (half << 3);
            const int m   = bm + row;
            #pragma unroll
            for (int nt = 0; nt < 4; nt++) {
                const int col = wn + (nt << 3) + (tig << 1);
                const int n   = bn + col;
                float2 v;
                v.x = acc[mt][nt][half ? 2 : 0] + bias[n];
                v.y = acc[mt][nt][half ? 3 : 1] + bias[n + 1];
                if (MODE == 1) {
                    *reinterpret_cast<float2*>(out + (size_t)m * Nw + n) = v;
                } else {
                    const int which = bn / C_;
                    const int c768  = n - which * C_;
                    const int h  = c768 >> 6;
                    const int d0 = c768 & 63;
                    const int bb = m >> 11;
                    const int t  = m & (T_ - 1);
                    float* dst = ((which == 0) ? g_q : (which == 1) ? g_k : g_v)
                                 + ((((size_t)bb * H_ + h) * T_ + t) << 6) + d0;
                    *reinterpret_cast<float2*>(dst) = v;
                }
            }
        }
    }
}

// ---------------------------------------------------------------------------
// Kernel 2: causal flash attention via mma.sync tf32.
// Block: 256 threads (8 warps), Q tile 128 rows (16/warp), KV tile 64.
// K smem [kv][d] pitch 68; V^T smem [d][kv] pitch 69; P smem [128][68].
// Q fragments register-resident; P round-trips smem for C->A frag remap.
// exp2 via 5-FMA polynomial; scale & log2e folded into Q at load.
// ---------------------------------------------------------------------------
#define KSP   68
#define VTP   69
#define PSP   68
#define KS_OFF 0
#define VT_OFF (64 * KSP)                   // 4352
#define PS_OFF (VT_OFF + 64 * VTP)          // 8768
#define ATTN_SMEM ((PS_OFF + 128 * PSP) * 4)  // 69888 bytes

__global__ __launch_bounds__(256) void attn_mma_kernel()
{
    extern __shared__ float sm[];
    float* Ks = sm + KS_OFF;    // [64][KSP]   K tile, [kv][d]
    float* Vt = sm + VT_OFF;    // [64][VTP]   V tile transposed, [d][kv]
    float* Ps = sm + PS_OFF;    // [128][PSP]  Q (at start) then P

    const int tid  = threadIdx.x;
    const int wid  = tid >> 5;
    const int lane = tid & 31;
    const int g    = lane >> 2;
    const int tig  = lane & 3;

    const int qt    = (int)gridDim.x - 1 - (int)blockIdx.x;   // heavy first
    const int bh    = blockIdx.y;
    const int qbase = qt << 7;

    const float* Qg = g_q + (size_t)bh * T_ * DH_;
    const float* Kg = g_k + (size_t)bh * T_ * DH_;
    const float* Vg = g_v + (size_t)bh * T_ * DH_;

    // Load Q tile (scaled by 1/sqrt(Dh) * log2(e), tf32) into Ps
    const float qscale = 0.125f * 1.44269504f;
    #pragma unroll
    for (int p = 0; p < 8; p++) {
        const int idx = tid + (p << 8);        // 0..2047 float4s
        const int r   = idx >> 4;
        const int c4  = (idx & 15) << 2;
        float4 v = *reinterpret_cast<const float4*>(Qg + (size_t)(qbase + r) * DH_ + c4);
        Ps[r * PSP + c4 + 0] = to_tf32(v.x * qscale);
        Ps[r * PSP + c4 + 1] = to_tf32(v.y * qscale);
        Ps[r * PSP + c4 + 2] = to_tf32(v.z * qscale);
        Ps[r * PSP + c4 + 3] = to_tf32(v.w * qscale);
    }
    __syncthreads();

    // Extract Q fragments to registers (A-frags for all 8 k-steps)
    const int rq0 = (wid << 4) + g;
    uint32_t qf[8][4];
    #pragma unroll
    for (int kk = 0; kk < 8; kk++) {
        qf[kk][0] = __float_as_uint(Ps[rq0 * PSP + (kk << 3) + tig]);
        qf[kk][1] = __float_as_uint(Ps[(rq0 + 8) * PSP + (kk << 3) + tig]);
        qf[kk][2] = __float_as_uint(Ps[rq0 * PSP + (kk << 3) + tig + 4]);
        qf[kk][3] = __float_as_uint(Ps[(rq0 + 8) * PSP + (kk << 3) + tig + 4]);
    }

    const int row0 = qbase + rq0;      // global q row for c0/c1
    const int row1 = row0 + 8;         // for c2/c3

    float m0 = -1e30f, m1 = -1e30f, l0 = 0.0f, l1 = 0.0f;
    float of[8][4] = {};

    const int ntiles = (qbase >> 6) + 2;

    for (int kt = 0; kt < ntiles; kt++) {
        const int kvb = kt << 6;
        __syncthreads();   // everyone done with previous K/V (and Q frags at kt=0)

        // K tile: [kv][d], tf32
        #pragma unroll
        for (int p = 0; p < 4; p++) {
            const int idx = tid + (p << 8);    // 0..1023 float4s
            const int r   = idx >> 4;
            const int c4  = (idx & 15) << 2;
            float4 v = *reinterpret_cast<const float4*>(Kg + (size_t)(kvb + r) * DH_ + c4);
            Ks[r * KSP + c4 + 0] = to_tf32(v.x);
            Ks[r * KSP + c4 + 1] = to_tf32(v.y);
            Ks[r * KSP + c4 + 2] = to_tf32(v.z);
            Ks[r * KSP + c4 + 3] = to_tf32(v.w);
        }
        // V tile transposed: Vt[d][kv], tf32
        {
            const int c  = tid & 63;           // d
            const int r0 = (tid >> 6) << 4;    // kv base, 16 rows
            #pragma unroll
            for (int i = 0; i < 16; i++) {
                const int r = r0 + i;
                Vt[c * VTP + r] = to_tf32(Vg[(size_t)(kvb + r) * DH_ + c]);
            }
        }
        __syncthreads();

        // S = Q K^T
        float sf[8][4] = {};
        #pragma unroll
        for (int kk = 0; kk < 8; kk++) {
            #pragma unroll
            for (int nt = 0; nt < 8; nt++) {
                uint32_t bf[2];
                bf[0] = __float_as_uint(Ks[((nt << 3) + g) * KSP + (kk << 3) + tig]);
                bf[1] = __float_as_uint(Ks[((nt << 3) + g) * KSP + (kk << 3) + tig + 4]);
                mma_16x8x8(sf[nt], qf[kk], bf);
            }
        }

        // causal mask + row max
        float mt0 = -1e30f, mt1 = -1e30f;
        #pragma unroll
        for (int nt = 0; nt < 8; nt++) {
            const int col = kvb + (nt << 3) + (tig << 1);
            if (col > row0)     sf[nt][0] = -1e30f;
            if (col + 1 > row0) sf[nt][1] = -1e30f;
            if (col > row1)     sf[nt][2] = -1e30f;
            if (col + 1 > row1) sf[nt][3] = -1e30f;
            mt0 = fmaxf(mt0, fmaxf(sf[nt][0], sf[nt][1]));
            mt1 = fmaxf(mt1, fmaxf(sf[nt][2], sf[nt][3]));
        }
        mt0 = fmaxf(mt0, __shfl_xor_sync(0xffffffffu, mt0, 1));
        mt0 = fmaxf(mt0, __shfl_xor_sync(0xffffffffu, mt0, 2));
        mt1 = fmaxf(mt1, __shfl_xor_sync(0xffffffffu, mt1, 1));
        mt1 = fmaxf(mt1, __shfl_xor_sync(0xffffffffu, mt1, 2));

        const float m0n = fmaxf(m0, mt0);
        const float m1n = fmaxf(m1, mt1);
        const float corr0 = fexp2(m0 - m0n);
        const float corr1 = fexp2(m1 - m1n);
        m0 = m0n; m1 = m1n;

        // exponentiate, accumulate partial row sums, store P (tf32)
        float rs0 = 0.0f, rs1 = 0.0f;
        #pragma unroll
        for (int nt = 0; nt < 8; nt++) {
            const float p0 = fexp2(sf[nt][0] - m0);
            const float p1 = fexp2(sf[nt][1] - m0);
            const float p2 = fexp2(sf[nt][2] - m1);
            const float p3 = fexp2(sf[nt][3] - m1);
            rs0 += p0 + p1;
            rs1 += p2 + p3;
            float2 v01; v01.x = to_tf32(p0); v01.y = to_tf32(p1);
            float2 v23; v23.x = to_tf32(p2); v23.y = to_tf32(p3);
            *reinterpret_cast<float2*>(&Ps[rq0 * PSP + (nt << 3) + (tig << 1)]) = v01;
            *reinterpret_cast<float2*>(&Ps[(rq0 + 8) * PSP + (nt << 3) + (tig << 1)]) = v23;
        }
        l0 = l0 * corr0 + rs0;
        l1 = l1 * corr1 + rs1;

        // rescale O
        #pragma unroll
        for (int nt = 0; nt < 8; nt++) {
            of[nt][0] *= corr0; of[nt][1] *= corr0;
            of[nt][2] *= corr1; of[nt][3] *= corr1;
        }
        __syncwarp();

        // O += P V
        #pragma unroll
        for (int kk = 0; kk < 8; kk++) {
            uint32_t af[4];
            af[0] = __float_as_uint(Ps[rq0 * PSP + (kk << 3) + tig]);
            af[1] = __float_as_uint(Ps[(rq0 + 8) * PSP + (kk << 3) + tig]);
            af[2] = __float_as_uint(Ps[rq0 * PSP + (kk << 3) + tig + 4]);
            af[3] = __float_as_uint(Ps[(rq0 + 8) * PSP + (kk << 3) + tig + 4]);
            #pragma unroll
            for (int nt = 0; nt < 8; nt++) {
                uint32_t bf[2];
                bf[0] = __float_as_uint(Vt[((nt << 3) + g) * VTP + (kk << 3) + tig]);
                bf[1] = __float_as_uint(Vt[((nt << 3) + g) * VTP + (kk << 3) + tig + 4]);
                mma_16x8x8(of[nt], af, bf);
            }
        }
        __syncwarp();
    }

    // finalize: reduce l across the 4-lane group, normalize, write
    l0 += __shfl_xor_sync(0xffffffffu, l0, 1);
    l0 += __shfl_xor_sync(0xffffffffu, l0, 2);
    l1 += __shfl_xor_sync(0xffffffffu, l1, 1);
    l1 += __shfl_xor_sync(0xffffffffu, l1, 2);
    const float inv0 = 1.0f / l0;
    const float inv1 = 1.0f / l1;

    const int b = bh / H_;
    const int h = bh - b * H_;
    float* y0 = g_y + ((size_t)b * T_ + row0) * C_ + h * DH_;
    float* y1 = g_y + ((size_t)b * T_ + row1) * C_ + h * DH_;
    #pragma unroll
    for (int nt = 0; nt < 8; nt++) {
        const int d = (nt << 3) + (tig << 1);
        float2 v0; v0.x = of[nt][0] * inv0; v0.y = of[nt][1] * inv0;
        float2 v1; v1.x = of[nt][2] * inv1; v1.y = of[nt][3] * inv1;
        *reinterpret_cast<float2*>(y0 + d) = v0;
        *reinterpret_cast<float2*>(y1 + d) = v1;
    }
}

// ---------------------------------------------------------------------------
// Launch
// ---------------------------------------------------------------------------
extern "C" void kernel_launch(void* const* d_in, const int* in_sizes, int n_in,
                              void* d_out, int out_size)
{
    const float* x      = (const float*)d_in[0];
    const float* w_attn = (const float*)d_in[1];
    const float* b_attn = (const float*)d_in[2];
    const float* w_proj = (const float*)d_in[3];
    const float* b_proj = (const float*)d_in[4];
    float* out = (float*)d_out;

    cudaFuncSetAttribute(attn_mma_kernel,
                         cudaFuncAttributeMaxDynamicSharedMemorySize, ATTN_SMEM);

    dim3 g1(NQKV_ / 128, M_ / 128);   // (18, 64)
    mm_mma_kernel<0><<<g1, 256>>>(x, w_attn, b_attn, nullptr, NQKV_);

    dim3 g2(T_ / 128, B_ * H_);       // (16, 48)
    attn_mma_kernel<<<g2, 256, ATTN_SMEM>>>();

    dim3 g3(C_ / 128, M_ / 128);      // (6, 64)
    mm_mma_kernel<1><<<g3, 256>>>(nullptr, w_proj, b_proj, out, C_);
}

// round 6
// speedup vs baseline: 4.0617x; 1.2865x over previous
#include <cuda_runtime.h>
#include <cuda_bf16.h>
#include <cstdint>

// Problem constants
#define B_    4
#define T_    2048
#define C_    768
#define H_    12
#define DH_   64
#define M_    (B_ * T_)      // 8192 rows
#define NQKV_ (3 * C_)       // 2304

// Scratch (allocation-free rule: __device__ globals)
__device__ float g_q[B_ * H_ * T_ * DH_];   // [b,h,t,d] (tf32-valued, q pre-scaled)
__device__ float g_k[B_ * H_ * T_ * DH_];
__device__ float g_v[B_ * H_ * T_ * DH_];
__device__ float g_y[M_ * C_];              // attention output (tf32-valued)
__device__ float g_xt[M_ * C_];             // x pre-converted to tf32
__device__ float g_wat[C_ * NQKV_];         // w_attn tf32
__device__ float g_wpt[C_ * C_];            // w_proj tf32

static __device__ __forceinline__ float to_tf32(float x) {
    float r;
    asm("cvt.rna.tf32.f32 %0, %1;" : "=f"(r) : "f"(x));
    return r;
}

static __device__ __forceinline__ uint32_t smem_u32(const void* p) {
    uint32_t a;
    asm("{ .reg .u64 t; cvta.to.shared.u64 t, %1; cvt.u32.u64 %0, t; }"
        : "=r"(a) : "l"(p));
    return a;
}

static __device__ __forceinline__ void cp16(uint32_t saddr, const void* g) {
    asm volatile("cp.async.cg.shared.global [%0], [%1], 16;"
                 :: "r"(saddr), "l"(g) : "memory");
}
static __device__ __forceinline__ void cp_commit() {
    asm volatile("cp.async.commit_group;" ::: "memory");
}
template<int N>
static __device__ __forceinline__ void cp_wait() {
    asm volatile("cp.async.wait_group %0;" :: "n"(N) : "memory");
}

static __device__ __forceinline__ void mma_16x8x8(float* c, const uint32_t* a,
                                                  const uint32_t* b) {
    asm volatile(
        "mma.sync.aligned.m16n8k8.row.col.f32.tf32.tf32.f32 "
        "{%0,%1,%2,%3}, {%4,%5,%6,%7}, {%8,%9}, {%0,%1,%2,%3};"
        : "+f"(c[0]), "+f"(c[1]), "+f"(c[2]), "+f"(c[3])
        : "r"(a[0]), "r"(a[1]), "r"(a[2]), "r"(a[3]), "r"(b[0]), "r"(b[1]));
}

// Fast exp2 on the FMA pipe (degree-5 minimax on [0,1)).
static __device__ __forceinline__ float fexp2(float x) {
    x = fmaxf(x, -126.0f);
    float fi = floorf(x);
    float f = x - fi;
    float p = fmaf(f, 0.00187757f, 0.00898934f);
    p = fmaf(f, p, 0.05582995f);
    p = fmaf(f, p, 0.24015361f);
    p = fmaf(f, p, 0.69315308f);
    p = fmaf(f, p, 1.0f);
    return p * __int_as_float(((int)fi + 127) << 23);
}

// ---------------------------------------------------------------------------
// Elementwise tf32 pre-conversion (RNA)
// ---------------------------------------------------------------------------
__global__ __launch_bounds__(256) void cvt_kernel(const float* __restrict__ in,
                                                  float* __restrict__ out)
{
    const int i = blockIdx.x * 256 + threadIdx.x;
    float4 v = reinterpret_cast<const float4*>(in)[i];
    v.x = to_tf32(v.x); v.y = to_tf32(v.y);
    v.z = to_tf32(v.z); v.w = to_tf32(v.w);
    reinterpret_cast<float4*>(out)[i] = v;
}

// ---------------------------------------------------------------------------
// tf32 mma.sync GEMM, cp.async double-buffered. 128x128 tile, BK=32.
// A (pre-tf32) [.,C_] row-major -> smem [128][36]; B (pre-tf32) [k][n] -> smem
// [32][136] (no transpose; frag bank pattern 8*tig+g, conflict-free).
// MODE 0: epilogue scatters q/k/v [b,h,t,d], q scaled by 1/8*log2e, all tf32.
// MODE 1: epilogue -> out (+bias), plain fp32.
// ---------------------------------------------------------------------------
#define BK      32
#define NCHUNK  (C_ / BK)    // 24
#define APITCH  36
#define BPITCH  136
#define MM_AS0  0
#define MM_AS1  (128 * APITCH)                 // 4608
#define MM_BS0  (2 * 128 * APITCH)             // 9216
#define MM_BS1  (MM_BS0 + 32 * BPITCH)         // 13568
#define MM_SMEM ((MM_BS0 + 2 * 32 * BPITCH) * 4)  // 71680 bytes

template<int MODE>
__global__ __launch_bounds__(256) void mm_mma_kernel(
    const float* __restrict__ A, const float* __restrict__ Wm,
    const float* __restrict__ bias, float* __restrict__ out, int Nw)
{
    extern __shared__ float sm[];
    const uint32_t sb = smem_u32(sm);

    const int tid  = threadIdx.x;
    const int wid  = tid >> 5;
    const int lane = tid & 31;
    const int g    = lane >> 2;
    const int tig  = lane & 3;

    const int bn = blockIdx.x << 7;
    const int bm = blockIdx.y << 7;
    const int wm = (wid >> 2) << 6;
    const int wn = (wid & 3) << 5;

    const uint32_t Aoff[2] = {MM_AS0, MM_AS1};
    const uint32_t Boff[2] = {MM_BS0, MM_BS1};

    // cp.async load of one K-chunk into buffer `buf`
    auto issue = [&](int k0, int bufA, int bufB) {
        // A: 128 rows x 32 floats = 1024 x 16B, 4 per thread
        #pragma unroll
        for (int p = 0; p < 4; p++) {
            const int idx = tid + (p << 8);
            const int r   = idx >> 3;
            const int s4  = (idx & 7) << 2;
            cp16(sb + (uint32_t)(bufA + r * APITCH + s4) * 4,
                 A + (size_t)(bm + r) * C_ + k0 + s4);
        }
        // B: 32 rows x 128 floats = 1024 x 16B, 4 per thread
        #pragma unroll
        for (int p = 0; p < 4; p++) {
            const int idx = tid + (p << 8);
            const int r   = idx >> 5;
            const int s4  = (idx & 31) << 2;
            cp16(sb + (uint32_t)(bufB + r * BPITCH + s4) * 4,
                 Wm + (size_t)(k0 + r) * Nw + bn + s4);
        }
        cp_commit();
    };

    float acc[4][4][4] = {};

    issue(0, Aoff[0], Boff[0]);

    for (int it = 0; it < NCHUNK; ++it) {
        if (it + 1 < NCHUNK) {
            issue((it + 1) << 5, Aoff[(it + 1) & 1], Boff[(it + 1) & 1]);
            cp_wait<1>();
        } else {
            cp_wait<0>();
        }
        __syncthreads();

        const float* As = sm + Aoff[it & 1];
        const float* Bs = sm + Boff[it & 1];

        #pragma unroll
        for (int kk = 0; kk < BK; kk += 8) {
            uint32_t af[4][4], bf[4][2];
            #pragma unroll
            for (int mt = 0; mt < 4; mt++) {
                const int r = wm + (mt << 4) + g;
                af[mt][0] = __float_as_uint(As[r * APITCH + kk + tig]);
                af[mt][1] = __float_as_uint(As[(r + 8) * APITCH + kk + tig]);
                af[mt][2] = __float_as_uint(As[r * APITCH + kk + tig + 4]);
                af[mt][3] = __float_as_uint(As[(r + 8) * APITCH + kk + tig + 4]);
            }
            #pragma unroll
            for (int nt = 0; nt < 4; nt++) {
                const int c = wn + (nt << 3) + g;
                bf[nt][0] = __float_as_uint(Bs[(kk + tig) * BPITCH + c]);
                bf[nt][1] = __float_as_uint(Bs[(kk + tig + 4) * BPITCH + c]);
            }
            #pragma unroll
            for (int mt = 0; mt < 4; mt++)
                #pragma unroll
                for (int nt = 0; nt < 4; nt++)
                    mma_16x8x8(acc[mt][nt], af[mt], bf[nt]);
        }
        __syncthreads();
    }

    const float qscale = 0.125f * 1.44269504f;
    #pragma unroll
    for (int mt = 0; mt < 4; mt++) {
        #pragma unroll
        for (int half = 0; half < 2; half++) {
            const int row = wm + (mt << 4) + g + (half << 3);
            const int m   = bm + row;
            #pragma unroll
            for (int nt = 0; nt < 4; nt++) {
                const int col = wn + (nt << 3) + (tig << 1);
                const int n   = bn + col;
                float2 v;
                v.x = acc[mt][nt][half ? 2 : 0] + bias[n];
                v.y = acc[mt][nt][half ? 3 : 1] + bias[n + 1];
                if (MODE == 1) {
                    *reinterpret_cast<float2*>(out + (size_t)m * Nw + n) = v;
                } else {
                    const int which = bn / C_;
                    if (which == 0) { v.x *= qscale; v.y *= qscale; }
                    v.x = to_tf32(v.x); v.y = to_tf32(v.y);
                    const int c768 = n - which * C_;
                    const int h  = c768 >> 6;
                    const int d0 = c768 & 63;
                    const int bb = m >> 11;
                    const int t  = m & (T_ - 1);
                    float* dst = ((which == 0) ? g_q : (which == 1) ? g_k : g_v)
                                 + ((((size_t)bb * H_ + h) * T_ + t) << 6) + d0;
                    *reinterpret_cast<float2*>(dst) = v;
                }
            }
        }
    }
}

// ---------------------------------------------------------------------------
// Causal flash attention via mma.sync tf32.
// 256 threads (8 warps), Q tile 128 (16 rows/warp), KV tile 64.
// Q in its own smem region (frags re-read per tile; fewer regs -> 2 CTAs/SM).
// Inputs are pre-tf32 (q pre-scaled) -> no cvt on loads; cp.async for Q and K.
// ---------------------------------------------------------------------------
#define QSP   68
#define KSP   68
#define VTP   69
#define PSP   68
#define QS_OFF 0
#define KS_OFF (128 * QSP)                    // 8704
#define VT_OFF (KS_OFF + 64 * KSP)            // 13056
#define PS_OFF (VT_OFF + 64 * VTP)            // 17472
#define ATTN_SMEM ((PS_OFF + 128 * PSP) * 4)  // 104704 bytes

__global__ __launch_bounds__(256, 2) void attn_mma_kernel()
{
    extern __shared__ float sm[];
    const uint32_t sb = smem_u32(sm);
    float* Qs = sm + QS_OFF;
    float* Ks = sm + KS_OFF;
    float* Vt = sm + VT_OFF;
    float* Ps = sm + PS_OFF;

    const int tid  = threadIdx.x;
    const int wid  = tid >> 5;
    const int lane = tid & 31;
    const int g    = lane >> 2;
    const int tig  = lane & 3;

    const int qt    = (int)gridDim.x - 1 - (int)blockIdx.x;   // heavy first
    const int bh    = blockIdx.y;
    const int qbase = qt << 7;

    const float* Qg = g_q + (size_t)bh * T_ * DH_;
    const float* Kg = g_k + (size_t)bh * T_ * DH_;
    const float* Vg = g_v + (size_t)bh * T_ * DH_;

    // Q tile via cp.async: 128 rows x 64 floats = 2048 x 16B, 8 per thread
    #pragma unroll
    for (int p = 0; p < 8; p++) {
        const int idx = tid + (p << 8);
        const int r   = idx >> 4;
        const int s4  = (idx & 15) << 2;
        cp16(sb + (uint32_t)(QS_OFF + r * QSP + s4) * 4,
             Qg + (size_t)(qbase + r) * DH_ + s4);
    }
    cp_commit();

    const int rq0  = (wid << 4) + g;
    const int row0 = qbase + rq0;
    const int row1 = row0 + 8;

    float m0 = -1e30f, m1 = -1e30f, l0 = 0.0f, l1 = 0.0f;
    float of[8][4] = {};

    const int ntiles = (qbase >> 6) + 2;

    cp_wait<0>();
    __syncthreads();

    for (int kt = 0; kt < ntiles; kt++) {
        const int kvb = kt << 6;
        __syncthreads();   // previous tile's compute done; K/V smem reusable

        // K tile via cp.async: 64 rows x 64 floats = 1024 x 16B, 4 per thread
        #pragma unroll
        for (int p = 0; p < 4; p++) {
            const int idx = tid + (p << 8);
            const int r   = idx >> 4;
            const int s4  = (idx & 15) << 2;
            cp16(sb + (uint32_t)(KS_OFF + r * KSP + s4) * 4,
                 Kg + (size_t)(kvb + r) * DH_ + s4);
        }
        cp_commit();
        // V tile transposed (scalar, overlaps the async K load)
        {
            const int c  = tid & 63;
            const int r0 = (tid >> 6) << 4;
            #pragma unroll
            for (int i = 0; i < 16; i++) {
                const int r = r0 + i;
                Vt[c * VTP + r] = Vg[(size_t)(kvb + r) * DH_ + c];
            }
        }
        cp_wait<0>();
        __syncthreads();

        // S = Q K^T
        float sf[8][4] = {};
        #pragma unroll
        for (int kk = 0; kk < 8; kk++) {
            uint32_t qa[4];
            qa[0] = __float_as_uint(Qs[rq0 * QSP + (kk << 3) + tig]);
            qa[1] = __float_as_uint(Qs[(rq0 + 8) * QSP + (kk << 3) + tig]);
            qa[2] = __float_as_uint(Qs[rq0 * QSP + (kk << 3) + tig + 4]);
            qa[3] = __float_as_uint(Qs[(rq0 + 8) * QSP + (kk << 3) + tig + 4]);
            #pragma unroll
            for (int nt = 0; nt < 8; nt++) {
                uint32_t bf[2];
                bf[0] = __float_as_uint(Ks[((nt << 3) + g) * KSP + (kk << 3) + tig]);
                bf[1] = __float_as_uint(Ks[((nt << 3) + g) * KSP + (kk << 3) + tig + 4]);
                mma_16x8x8(sf[nt], qa, bf);
            }
        }

        // causal mask + row max
        float mt0 = -1e30f, mt1 = -1e30f;
        #pragma unroll
        for (int nt = 0; nt < 8; nt++) {
            const int col = kvb + (nt << 3) + (tig << 1);
            if (col > row0)     sf[nt][0] = -1e30f;
            if (col + 1 > row0) sf[nt][1] = -1e30f;
            if (col > row1)     sf[nt][2] = -1e30f;
            if (col + 1 > row1) sf[nt][3] = -1e30f;
            mt0 = fmaxf(mt0, fmaxf(sf[nt][0], sf[nt][1]));
            mt1 = fmaxf(mt1, fmaxf(sf[nt][2], sf[nt][3]));
        }
        mt0 = fmaxf(mt0, __shfl_xor_sync(0xffffffffu, mt0, 1));
        mt0 = fmaxf(mt0, __shfl_xor_sync(0xffffffffu, mt0, 2));
        mt1 = fmaxf(mt1, __shfl_xor_sync(0xffffffffu, mt1, 1));
        mt1 = fmaxf(mt1, __shfl_xor_sync(0xffffffffu, mt1, 2));

        const float m0n = fmaxf(m0, mt0);
        const float m1n = fmaxf(m1, mt1);
        const float corr0 = fexp2(m0 - m0n);
        const float corr1 = fexp2(m1 - m1n);
        m0 = m0n; m1 = m1n;

        // exponentiate, partial row sums, store P (tf32)
        float rs0 = 0.0f, rs1 = 0.0f;
        #pragma unroll
        for (int nt = 0; nt < 8; nt++) {
            const float p0 = fexp2(sf[nt][0] - m0);
            const float p1 = fexp2(sf[nt][1] - m0);
            const float p2 = fexp2(sf[nt][2] - m1);
            const float p3 = fexp2(sf[nt][3] - m1);
            rs0 += p0 + p1;
            rs1 += p2 + p3;
            float2 v01; v01.x = to_tf32(p0); v01.y = to_tf32(p1);
            float2 v23; v23.x = to_tf32(p2); v23.y = to_tf32(p3);
            *reinterpret_cast<float2*>(&Ps[rq0 * PSP + (nt << 3) + (tig << 1)]) = v01;
            *reinterpret_cast<float2*>(&Ps[(rq0 + 8) * PSP + (nt << 3) + (tig << 1)]) = v23;
        }
        l0 = l0 * corr0 + rs0;
        l1 = l1 * corr1 + rs1;

        #pragma unroll
        for (int nt = 0; nt < 8; nt++) {
            of[nt][0] *= corr0; of[nt][1] *= corr0;
            of[nt][2] *= corr1; of[nt][3] *= corr1;
        }
        __syncwarp();

        // O += P V
        #pragma unroll
        for (int kk = 0; kk < 8; kk++) {
            uint32_t af[4];
            af[0] = __float_as_uint(Ps[rq0 * PSP + (kk << 3) + tig]);
            af[1] = __float_as_uint(Ps[(rq0 + 8) * PSP + (kk << 3) + tig]);
            af[2] = __float_as_uint(Ps[rq0 * PSP + (kk << 3) + tig + 4]);
            af[3] = __float_as_uint(Ps[(rq0 + 8) * PSP + (kk << 3) + tig + 4]);
            #pragma unroll
            for (int nt = 0; nt < 8; nt++) {
                uint32_t bf[2];
                bf[0] = __float_as_uint(Vt[((nt << 3) + g) * VTP + (kk << 3) + tig]);
                bf[1] = __float_as_uint(Vt[((nt << 3) + g) * VTP + (kk << 3) + tig + 4]);
                mma_16x8x8(of[nt], af, bf);
            }
        }
        __syncwarp();
    }

    l0 += __shfl_xor_sync(0xffffffffu, l0, 1);
    l0 += __shfl_xor_sync(0xffffffffu, l0, 2);
    l1 += __shfl_xor_sync(0xffffffffu, l1, 1);
    l1 += __shfl_xor_sync(0xffffffffu, l1, 2);
    const float inv0 = 1.0f / l0;
    const float inv1 = 1.0f / l1;

    const int b = bh / H_;
    const int h = bh - b * H_;
    float* y0 = g_y + ((size_t)b * T_ + row0) * C_ + h * DH_;
    float* y1 = g_y + ((size_t)b * T_ + row1) * C_ + h * DH_;
    #pragma unroll
    for (int nt = 0; nt < 8; nt++) {
        const int d = (nt << 3) + (tig << 1);
        float2 v0; v0.x = to_tf32(of[nt][0] * inv0); v0.y = to_tf32(of[nt][1] * inv0);
        float2 v1; v1.x = to_tf32(of[nt][2] * inv1); v1.y = to_tf32(of[nt][3] * inv1);
        *reinterpret_cast<float2*>(y0 + d) = v0;
        *reinterpret_cast<float2*>(y1 + d) = v1;
    }
}

// ---------------------------------------------------------------------------
// Launch
// ---------------------------------------------------------------------------
extern "C" void kernel_launch(void* const* d_in, const int* in_sizes, int n_in,
                              void* d_out, int out_size)
{
    const float* x      = (const float*)d_in[0];
    const float* w_attn = (const float*)d_in[1];
    const float* b_attn = (const float*)d_in[2];
    const float* w_proj = (const float*)d_in[3];
    const float* b_proj = (const float*)d_in[4];
    float* out = (float*)d_out;

    cudaFuncSetAttribute(mm_mma_kernel<0>,
                         cudaFuncAttributeMaxDynamicSharedMemorySize, MM_SMEM);
    cudaFuncSetAttribute(mm_mma_kernel<1>,
                         cudaFuncAttributeMaxDynamicSharedMemorySize, MM_SMEM);
    cudaFuncSetAttribute(attn_mma_kernel,
                         cudaFuncAttributeMaxDynamicSharedMemorySize, ATTN_SMEM);

    float *g_xt_p, *g_wat_p, *g_wpt_p;
    cudaGetSymbolAddress((void**)&g_xt_p,  g_xt);
    cudaGetSymbolAddress((void**)&g_wat_p, g_wat);
    cudaGetSymbolAddress((void**)&g_wpt_p, g_wpt);

    cvt_kernel<<<(M_ * C_) / 1024, 256>>>(x, g_xt_p);
    cvt_kernel<<<(C_ * NQKV_) / 1024, 256>>>(w_attn, g_wat_p);
    cvt_kernel<<<(C_ * C_) / 1024, 256>>>(w_proj, g_wpt_p);

    dim3 g1(NQKV_ / 128, M_ / 128);   // (18, 64)
    mm_mma_kernel<0><<<g1, 256, MM_SMEM>>>(g_xt_p, g_wat_p, b_attn, nullptr, NQKV_);

    dim3 g2(T_ / 128, B_ * H_);       // (16, 48)
    attn_mma_kernel<<<g2, 256, ATTN_SMEM>>>();

    dim3 g3(C_ / 128, M_ / 128);      // (6, 64)
    float* g_y_p; cudaGetSymbolAddress((void**)&g_y_p, g_y);
    mm_mma_kernel<1><<<g3, 256, MM_SMEM>>>(g_y_p, g_wpt_p, b_proj, out, C_);
}

// round 7
// speedup vs baseline: 4.5580x; 1.1222x over previous
#include <cuda_runtime.h>
#include <cuda_bf16.h>
#include <cstdint>

// Problem constants
#define B_    4
#define T_    2048
#define C_    768
#define H_    12
#define DH_   64
#define M_    (B_ * T_)      // 8192 rows
#define NQKV_ (3 * C_)       // 2304

// Scratch (allocation-free rule: __device__ globals)
__device__ float g_q[B_ * H_ * T_ * DH_];   // [b,h,t,d] (tf32-valued, q pre-scaled)
__device__ float g_k[B_ * H_ * T_ * DH_];
__device__ float g_v[B_ * H_ * T_ * DH_];
__device__ float g_y[M_ * C_];              // attention output (tf32-valued)
__device__ float g_xt[M_ * C_];             // x pre-converted to tf32
__device__ float g_wat[C_ * NQKV_];         // w_attn tf32
__device__ float g_wpt[C_ * C_];            // w_proj tf32

static __device__ __forceinline__ float to_tf32(float x) {
    float r;
    asm("cvt.rna.tf32.f32 %0, %1;" : "=f"(r) : "f"(x));
    return r;
}

static __device__ __forceinline__ uint32_t smem_u32(const void* p) {
    uint32_t a;
    asm("{ .reg .u64 t; cvta.to.shared.u64 t, %1; cvt.u32.u64 %0, t; }"
        : "=r"(a) : "l"(p));
    return a;
}

static __device__ __forceinline__ void cp16(uint32_t saddr, const void* g) {
    asm volatile("cp.async.cg.shared.global [%0], [%1], 16;"
                 :: "r"(saddr), "l"(g) : "memory");
}
static __device__ __forceinline__ void cp_commit() {
    asm volatile("cp.async.commit_group;" ::: "memory");
}
template<int N>
static __device__ __forceinline__ void cp_wait() {
    asm volatile("cp.async.wait_group %0;" :: "n"(N) : "memory");
}

static __device__ __forceinline__ void mma_16x8x8(float* c, const uint32_t* a,
                                                  const uint32_t* b) {
    asm volatile(
        "mma.sync.aligned.m16n8k8.row.col.f32.tf32.tf32.f32 "
        "{%0,%1,%2,%3}, {%4,%5,%6,%7}, {%8,%9}, {%0,%1,%2,%3};"
        : "+f"(c[0]), "+f"(c[1]), "+f"(c[2]), "+f"(c[3])
        : "r"(a[0]), "r"(a[1]), "r"(a[2]), "r"(a[3]), "r"(b[0]), "r"(b[1]));
}

// Fast exp2 on the FMA pipe (degree-5 minimax on [0,1)).
static __device__ __forceinline__ float fexp2(float x) {
    x = fmaxf(x, -126.0f);
    float fi = floorf(x);
    float f = x - fi;
    float p = fmaf(f, 0.00187757f, 0.00898934f);
    p = fmaf(f, p, 0.05582995f);
    p = fmaf(f, p, 0.24015361f);
    p = fmaf(f, p, 0.69315308f);
    p = fmaf(f, p, 1.0f);
    return p * __int_as_float(((int)fi + 127) << 23);
}

// ---------------------------------------------------------------------------
// Elementwise tf32 pre-conversion (RNA)
// ---------------------------------------------------------------------------
__global__ __launch_bounds__(256) void cvt_kernel(const float* __restrict__ in,
                                                  float* __restrict__ out)
{
    const int i = blockIdx.x * 256 + threadIdx.x;
    float4 v = reinterpret_cast<const float4*>(in)[i];
    v.x = to_tf32(v.x); v.y = to_tf32(v.y);
    v.z = to_tf32(v.z); v.w = to_tf32(v.w);
    reinterpret_cast<float4*>(out)[i] = v;
}

// ---------------------------------------------------------------------------
// tf32 mma.sync GEMM, 3-stage cp.async pipeline. 128x128 tile, BK=32.
// A (pre-tf32) [.,C_] row-major -> smem [128][36]; B (pre-tf32) [k][n] -> smem
// [32][136] (frag bank pattern conflict-free).
// MODE 0: epilogue scatters q/k/v [b,h,t,d], q scaled by 1/8*log2e, all tf32.
// MODE 1: epilogue -> out (+bias), plain fp32.
// ---------------------------------------------------------------------------
#define BK       32
#define NCHUNK   (C_ / BK)    // 24
#define APITCH   36
#define BPITCH   136
#define MM_STAGE (128 * APITCH + 32 * BPITCH)   // 8960 floats
#define MM_SMEM  (3 * MM_STAGE * 4)             // 107520 bytes

template<int MODE>
__global__ __launch_bounds__(256, 2) void mm_mma_kernel(
    const float* __restrict__ A, const float* __restrict__ Wm,
    const float* __restrict__ bias, float* __restrict__ out, int Nw)
{
    extern __shared__ float sm[];
    const uint32_t sb = smem_u32(sm);

    const int tid  = threadIdx.x;
    const int wid  = tid >> 5;
    const int lane = tid & 31;
    const int g    = lane >> 2;
    const int tig  = lane & 3;

    const int bn = blockIdx.x << 7;
    const int bm = blockIdx.y << 7;
    const int wm = (wid >> 2) << 6;
    const int wn = (wid & 3) << 5;

    auto issue = [&](int k0, int st) {
        const uint32_t bufA = st * MM_STAGE;
        const uint32_t bufB = bufA + 128 * APITCH;
        #pragma unroll
        for (int p = 0; p < 4; p++) {
            const int idx = tid + (p << 8);
            const int r   = idx >> 3;
            const int s4  = (idx & 7) << 2;
            cp16(sb + (uint32_t)(bufA + r * APITCH + s4) * 4,
                 A + (size_t)(bm + r) * C_ + k0 + s4);
        }
        #pragma unroll
        for (int p = 0; p < 4; p++) {
            const int idx = tid + (p << 8);
            const int r   = idx >> 5;
            const int s4  = (idx & 31) << 2;
            cp16(sb + (uint32_t)(bufB + r * BPITCH + s4) * 4,
                 Wm + (size_t)(k0 + r) * Nw + bn + s4);
        }
        cp_commit();
    };

    float acc[4][4][4] = {};

    issue(0, 0);
    issue(BK, 1);

    int st = 0;
    for (int it = 0; it < NCHUNK; ++it) {
        if (it + 2 < NCHUNK) {
            issue((it + 2) << 5, (st + 2) % 3);
            cp_wait<2>();
        } else if (it + 1 < NCHUNK) {
            cp_wait<1>();
        } else {
            cp_wait<0>();
        }
        __syncthreads();

        const float* As = sm + st * MM_STAGE;
        const float* Bs = As + 128 * APITCH;

        #pragma unroll
        for (int kk = 0; kk < BK; kk += 8) {
            uint32_t af[4][4], bf[4][2];
            #pragma unroll
            for (int mt = 0; mt < 4; mt++) {
                const int r = wm + (mt << 4) + g;
                af[mt][0] = __float_as_uint(As[r * APITCH + kk + tig]);
                af[mt][1] = __float_as_uint(As[(r + 8) * APITCH + kk + tig]);
                af[mt][2] = __float_as_uint(As[r * APITCH + kk + tig + 4]);
                af[mt][3] = __float_as_uint(As[(r + 8) * APITCH + kk + tig + 4]);
            }
            #pragma unroll
            for (int nt = 0; nt < 4; nt++) {
                const int c = wn + (nt << 3) + g;
                bf[nt][0] = __float_as_uint(Bs[(kk + tig) * BPITCH + c]);
                bf[nt][1] = __float_as_uint(Bs[(kk + tig + 4) * BPITCH + c]);
            }
            #pragma unroll
            for (int mt = 0; mt < 4; mt++)
                #pragma unroll
                for (int nt = 0; nt < 4; nt++)
                    mma_16x8x8(acc[mt][nt], af[mt], bf[nt]);
        }
        __syncthreads();
        st = (st + 1) % 3;
    }

    const float qscale = 0.125f * 1.44269504f;
    #pragma unroll
    for (int mt = 0; mt < 4; mt++) {
        #pragma unroll
        for (int half = 0; half < 2; half++) {
            const int row = wm + (mt << 4) + g + (half << 3);
            const int m   = bm + row;
            #pragma unroll
            for (int nt = 0; nt < 4; nt++) {
                const int col = wn + (nt << 3) + (tig << 1);
                const int n   = bn + col;
                float2 v;
                v.x = acc[mt][nt][half ? 2 : 0] + bias[n];
                v.y = acc[mt][nt][half ? 3 : 1] + bias[n + 1];
                if (MODE == 1) {
                    *reinterpret_cast<float2*>(out + (size_t)m * Nw + n) = v;
                } else {
                    const int which = bn / C_;
                    if (which == 0) { v.x *= qscale; v.y *= qscale; }
                    v.x = to_tf32(v.x); v.y = to_tf32(v.y);
                    const int c768 = n - which * C_;
                    const int h  = c768 >> 6;
                    const int d0 = c768 & 63;
                    const int bb = m >> 11;
                    const int t  = m & (T_ - 1);
                    float* dst = ((which == 0) ? g_q : (which == 1) ? g_k : g_v)
                                 + ((((size_t)bb * H_ + h) * T_ + t) << 6) + d0;
                    *reinterpret_cast<float2*>(dst) = v;
                }
            }
        }
    }
}

// ---------------------------------------------------------------------------
// Causal flash attention via mma.sync tf32.
// 256 threads (8 warps), Q tile 128 (16 rows/warp), KV tile 64.
// K [kv][68] and V [kv][72] both natural layout via cp.async (no transpose);
// pitch 72 makes the V B-fragment pattern conflict-free: bank = 8*tig+g+const.
// Inputs pre-tf32 (q pre-scaled by 0.125*log2e). 2 CTAs/SM.
// ---------------------------------------------------------------------------
#define QSP   68
#define KSP   68
#define VSP   72
#define PSP   68
#define QS_OFF 0
#define KS_OFF (128 * QSP)                    // 8704
#define VS_OFF (KS_OFF + 64 * KSP)            // 13056
#define PS_OFF (VS_OFF + 64 * VSP)            // 17664
#define ATTN_SMEM ((PS_OFF + 128 * PSP) * 4)  // 105472 bytes

__global__ __launch_bounds__(256, 2) void attn_mma_kernel()
{
    extern __shared__ float sm[];
    const uint32_t sb = smem_u32(sm);
    float* Qs = sm + QS_OFF;
    float* Ks = sm + KS_OFF;
    float* Vs = sm + VS_OFF;
    float* Ps = sm + PS_OFF;

    const int tid  = threadIdx.x;
    const int wid  = tid >> 5;
    const int lane = tid & 31;
    const int g    = lane >> 2;
    const int tig  = lane & 3;

    const int qt    = (int)gridDim.x - 1 - (int)blockIdx.x;   // heavy first
    const int bh    = blockIdx.y;
    const int qbase = qt << 7;

    const float* Qg = g_q + (size_t)bh * T_ * DH_;
    const float* Kg = g_k + (size_t)bh * T_ * DH_;
    const float* Vg = g_v + (size_t)bh * T_ * DH_;

    // Q tile via cp.async: 128 rows x 64 floats = 2048 x 16B, 8 per thread
    #pragma unroll
    for (int p = 0; p < 8; p++) {
        const int idx = tid + (p << 8);
        const int r   = idx >> 4;
        const int s4  = (idx & 15) << 2;
        cp16(sb + (uint32_t)(QS_OFF + r * QSP + s4) * 4,
             Qg + (size_t)(qbase + r) * DH_ + s4);
    }
    cp_commit();

    const int rq0  = (wid << 4) + g;
    const int row0 = qbase + rq0;
    const int row1 = row0 + 8;

    float m0 = -1e30f, m1 = -1e30f, l0 = 0.0f, l1 = 0.0f;
    float of[8][4] = {};

    const int ntiles = (qbase >> 6) + 2;

    cp_wait<0>();
    __syncthreads();

    for (int kt = 0; kt < ntiles; kt++) {
        const int kvb = kt << 6;
        __syncthreads();   // previous tile's compute done; K/V smem reusable

        // K and V tiles via cp.async: each 64 rows x 64 floats
        #pragma unroll
        for (int p = 0; p < 4; p++) {
            const int idx = tid + (p << 8);
            const int r   = idx >> 4;
            const int s4  = (idx & 15) << 2;
            cp16(sb + (uint32_t)(KS_OFF + r * KSP + s4) * 4,
                 Kg + (size_t)(kvb + r) * DH_ + s4);
        }
        #pragma unroll
        for (int p = 0; p < 4; p++) {
            const int idx = tid + (p << 8);
            const int r   = idx >> 4;
            const int s4  = (idx & 15) << 2;
            cp16(sb + (uint32_t)(VS_OFF + r * VSP + s4) * 4,
                 Vg + (size_t)(kvb + r) * DH_ + s4);
        }
        cp_commit();
        cp_wait<0>();
        __syncthreads();

        // S = Q K^T
        float sf[8][4] = {};
        #pragma unroll
        for (int kk = 0; kk < 8; kk++) {
            uint32_t qa[4];
            qa[0] = __float_as_uint(Qs[rq0 * QSP + (kk << 3) + tig]);
            qa[1] = __float_as_uint(Qs[(rq0 + 8) * QSP + (kk << 3) + tig]);
            qa[2] = __float_as_uint(Qs[rq0 * QSP + (kk << 3) + tig + 4]);
            qa[3] = __float_as_uint(Qs[(rq0 + 8) * QSP + (kk << 3) + tig + 4]);
            #pragma unroll
            for (int nt = 0; nt < 8; nt++) {
                uint32_t bf[2];
                bf[0] = __float_as_uint(Ks[((nt << 3) + g) * KSP + (kk << 3) + tig]);
                bf[1] = __float_as_uint(Ks[((nt << 3) + g) * KSP + (kk << 3) + tig + 4]);
                mma_16x8x8(sf[nt], qa, bf);
            }
        }

        // causal mask + row max
        float mt0 = -1e30f, mt1 = -1e30f;
        #pragma unroll
        for (int nt = 0; nt < 8; nt++) {
            const int col = kvb + (nt << 3) + (tig << 1);
            if (col > row0)     sf[nt][0] = -1e30f;
            if (col + 1 > row0) sf[nt][1] = -1e30f;
            if (col > row1)     sf[nt][2] = -1e30f;
            if (col + 1 > row1) sf[nt][3] = -1e30f;
            mt0 = fmaxf(mt0, fmaxf(sf[nt][0], sf[nt][1]));
            mt1 = fmaxf(mt1, fmaxf(sf[nt][2], sf[nt][3]));
        }
        mt0 = fmaxf(mt0, __shfl_xor_sync(0xffffffffu, mt0, 1));
        mt0 = fmaxf(mt0, __shfl_xor_sync(0xffffffffu, mt0, 2));
        mt1 = fmaxf(mt1, __shfl_xor_sync(0xffffffffu, mt1, 1));
        mt1 = fmaxf(mt1, __shfl_xor_sync(0xffffffffu, mt1, 2));

        const float m0n = fmaxf(m0, mt0);
        const float m1n = fmaxf(m1, mt1);
        const float corr0 = fexp2(m0 - m0n);
        const float corr1 = fexp2(m1 - m1n);
        m0 = m0n; m1 = m1n;

        // exponentiate, partial row sums, store P (tf32)
        float rs0 = 0.0f, rs1 = 0.0f;
        #pragma unroll
        for (int nt = 0; nt < 8; nt++) {
            const float p0 = fexp2(sf[nt][0] - m0);
            const float p1 = fexp2(sf[nt][1] - m0);
            const float p2 = fexp2(sf[nt][2] - m1);
            const float p3 = fexp2(sf[nt][3] - m1);
            rs0 += p0 + p1;
            rs1 += p2 + p3;
            float2 v01; v01.x = to_tf32(p0); v01.y = to_tf32(p1);
            float2 v23; v23.x = to_tf32(p2); v23.y = to_tf32(p3);
            *reinterpret_cast<float2*>(&Ps[rq0 * PSP + (nt << 3) + (tig << 1)]) = v01;
            *reinterpret_cast<float2*>(&Ps[(rq0 + 8) * PSP + (nt << 3) + (tig << 1)]) = v23;
        }
        l0 = l0 * corr0 + rs0;
        l1 = l1 * corr1 + rs1;

        #pragma unroll
        for (int nt = 0; nt < 8; nt++) {
            of[nt][0] *= corr0; of[nt][1] *= corr0;
            of[nt][2] *= corr1; of[nt][3] *= corr1;
        }
        __syncwarp();

        // O += P V   (V natural layout; B-frag = Vs[kv][d], conflict-free)
        #pragma unroll
        for (int kk = 0; kk < 8; kk++) {
            uint32_t af[4];
            af[0] = __float_as_uint(Ps[rq0 * PSP + (kk << 3) + tig]);
            af[1] = __float_as_uint(Ps[(rq0 + 8) * PSP + (kk << 3) + tig]);
            af[2] = __float_as_uint(Ps[rq0 * PSP + (kk << 3) + tig + 4]);
            af[3] = __float_as_uint(Ps[(rq0 + 8) * PSP + (kk << 3) + tig + 4]);
            #pragma unroll
            for (int nt = 0; nt < 8; nt++) {
                uint32_t bf[2];
                bf[0] = __float_as_uint(Vs[((kk << 3) + tig) * VSP + (nt << 3) + g]);
                bf[1] = __float_as_uint(Vs[((kk << 3) + tig + 4) * VSP + (nt << 3) + g]);
                mma_16x8x8(of[nt], af, bf);
            }
        }
        __syncwarp();
    }

    l0 += __shfl_xor_sync(0xffffffffu, l0, 1);
    l0 += __shfl_xor_sync(0xffffffffu, l0, 2);
    l1 += __shfl_xor_sync(0xffffffffu, l1, 1);
    l1 += __shfl_xor_sync(0xffffffffu, l1, 2);
    const float inv0 = 1.0f / l0;
    const float inv1 = 1.0f / l1;

    const int b = bh / H_;
    const int h = bh - b * H_;
    float* y0 = g_y + ((size_t)b * T_ + row0) * C_ + h * DH_;
    float* y1 = g_y + ((size_t)b * T_ + row1) * C_ + h * DH_;
    #pragma unroll
    for (int nt = 0; nt < 8; nt++) {
        const int d = (nt << 3) + (tig << 1);
        float2 v0; v0.x = to_tf32(of[nt][0] * inv0); v0.y = to_tf32(of[nt][1] * inv0);
        float2 v1; v1.x = to_tf32(of[nt][2] * inv1); v1.y = to_tf32(of[nt][3] * inv1);
        *reinterpret_cast<float2*>(y0 + d) = v0;
        *reinterpret_cast<float2*>(y1 + d) = v1;
    }
}

// ---------------------------------------------------------------------------
// Launch
// ---------------------------------------------------------------------------
extern "C" void kernel_launch(void* const* d_in, const int* in_sizes, int n_in,
                              void* d_out, int out_size)
{
    const float* x      = (const float*)d_in[0];
    const float* w_attn = (const float*)d_in[1];
    const float* b_attn = (const float*)d_in[2];
    const float* w_proj = (const float*)d_in[3];
    const float* b_proj = (const float*)d_in[4];
    float* out = (float*)d_out;

    cudaFuncSetAttribute(mm_mma_kernel<0>,
                         cudaFuncAttributeMaxDynamicSharedMemorySize, MM_SMEM);
    cudaFuncSetAttribute(mm_mma_kernel<1>,
                         cudaFuncAttributeMaxDynamicSharedMemorySize, MM_SMEM);
    cudaFuncSetAttribute(attn_mma_kernel,
                         cudaFuncAttributeMaxDynamicSharedMemorySize, ATTN_SMEM);

    float *g_xt_p, *g_wat_p, *g_wpt_p, *g_y_p;
    cudaGetSymbolAddress((void**)&g_xt_p,  g_xt);
    cudaGetSymbolAddress((void**)&g_wat_p, g_wat);
    cudaGetSymbolAddress((void**)&g_wpt_p, g_wpt);
    cudaGetSymbolAddress((void**)&g_y_p,   g_y);

    cvt_kernel<<<(M_ * C_) / 1024, 256>>>(x, g_xt_p);
    cvt_kernel<<<(C_ * NQKV_) / 1024, 256>>>(w_attn, g_wat_p);
    cvt_kernel<<<(C_ * C_) / 1024, 256>>>(w_proj, g_wpt_p);

    dim3 g1(NQKV_ / 128, M_ / 128);   // (18, 64)
    mm_mma_kernel<0><<<g1, 256, MM_SMEM>>>(g_xt_p, g_wat_p, b_attn, nullptr, NQKV_);

    dim3 g2(T_ / 128, B_ * H_);       // (16, 48)
    attn_mma_kernel<<<g2, 256, ATTN_SMEM>>>();

    dim3 g3(C_ / 128, M_ / 128);      // (6, 64)
    mm_mma_kernel<1><<<g3, 256, MM_SMEM>>>(g_y_p, g_wpt_p, b_proj, out, C_);
}

// round 8
// speedup vs baseline: 4.8079x; 1.0548x over previous
#include <cuda_runtime.h>
#include <cuda_bf16.h>
#include <cstdint>

// Problem constants
#define B_    4
#define T_    2048
#define C_    768
#define H_    12
#define DH_   64
#define M_    (B_ * T_)      // 8192 rows
#define NQKV_ (3 * C_)       // 2304

// Scratch (allocation-free rule: __device__ globals)
__device__ float g_q[B_ * H_ * T_ * DH_];   // [b,h,t,d] (tf32-valued, pre-scaled)
__device__ float g_k[B_ * H_ * T_ * DH_];   // [b,h,t,d]
__device__ float g_v[B_ * H_ * DH_ * T_];   // [b,h,d,t]  (TRANSPOSED)
__device__ float g_y[M_ * C_];              // attention output (tf32-valued)
__device__ float g_xt[M_ * C_];             // x pre-converted to tf32
__device__ float g_wat[NQKV_ * C_];         // w_attn^T tf32  [n][k]
__device__ float g_wpt[C_ * C_];            // w_proj^T tf32  [n][k]

static __device__ __forceinline__ float to_tf32(float x) {
    float r;
    asm("cvt.rna.tf32.f32 %0, %1;" : "=f"(r) : "f"(x));
    return r;
}

static __device__ __forceinline__ uint32_t smem_u32(const void* p) {
    uint32_t a;
    asm("{ .reg .u64 t; cvta.to.shared.u64 t, %1; cvt.u32.u64 %0, t; }"
        : "=r"(a) : "l"(p));
    return a;
}

static __device__ __forceinline__ void cp16(uint32_t saddr, const void* g) {
    asm volatile("cp.async.cg.shared.global [%0], [%1], 16;"
                 :: "r"(saddr), "l"(g) : "memory");
}
static __device__ __forceinline__ void cp_commit() {
    asm volatile("cp.async.commit_group;" ::: "memory");
}
template<int N>
static __device__ __forceinline__ void cp_wait() {
    asm volatile("cp.async.wait_group %0;" :: "n"(N) : "memory");
}

static __device__ __forceinline__ void ldsm_x4(uint32_t* r, uint32_t saddr) {
    asm volatile("ldmatrix.sync.aligned.m8n8.x4.shared.b16 {%0,%1,%2,%3}, [%4];"
                 : "=r"(r[0]), "=r"(r[1]), "=r"(r[2]), "=r"(r[3]) : "r"(saddr));
}

static __device__ __forceinline__ void mma_16x8x8(float* c, const uint32_t* a,
                                                  const uint32_t* b) {
    asm volatile(
        "mma.sync.aligned.m16n8k8.row.col.f32.tf32.tf32.f32 "
        "{%0,%1,%2,%3}, {%4,%5,%6,%7}, {%8,%9}, {%0,%1,%2,%3};"
        : "+f"(c[0]), "+f"(c[1]), "+f"(c[2]), "+f"(c[3])
        : "r"(a[0]), "r"(a[1]), "r"(a[2]), "r"(a[3]), "r"(b[0]), "r"(b[1]));
}

// Fast exp2 on the FMA pipe (degree-5 minimax on [0,1)).
static __device__ __forceinline__ float fexp2(float x) {
    x = fmaxf(x, -126.0f);
    float fi = floorf(x);
    float f = x - fi;
    float p = fmaf(f, 0.00187757f, 0.00898934f);
    p = fmaf(f, p, 0.05582995f);
    p = fmaf(f, p, 0.24015361f);
    p = fmaf(f, p, 0.69315308f);
    p = fmaf(f, p, 1.0f);
    return p * __int_as_float(((int)fi + 127) << 23);
}

// ---------------------------------------------------------------------------
// Elementwise tf32 pre-conversion (x) and tf32 transpose (weights)
// ---------------------------------------------------------------------------
__global__ __launch_bounds__(256) void cvt_kernel(const float* __restrict__ in,
                                                  float* __restrict__ out)
{
    const int i = blockIdx.x * 256 + threadIdx.x;
    float4 v = reinterpret_cast<const float4*>(in)[i];
    v.x = to_tf32(v.x); v.y = to_tf32(v.y);
    v.z = to_tf32(v.z); v.w = to_tf32(v.w);
    reinterpret_cast<float4*>(out)[i] = v;
}

// in [K][N] -> out [N][K], tf32. grid (N/32, K/32), 256 threads.
__global__ __launch_bounds__(256) void cvt_t_kernel(const float* __restrict__ in,
                                                    float* __restrict__ out,
                                                    int K, int N)
{
    __shared__ float t[32][33];
    const int tx = threadIdx.x & 31;
    const int ty = threadIdx.x >> 5;       // 0..7
    const int nb = blockIdx.x << 5;
    const int kb = blockIdx.y << 5;
    #pragma unroll
    for (int j = 0; j < 4; j++)
        t[ty + (j << 3)][tx] = in[(size_t)(kb + ty + (j << 3)) * N + nb + tx];
    __syncthreads();
    #pragma unroll
    for (int j = 0; j < 4; j++)
        out[(size_t)(nb + ty + (j << 3)) * K + kb + tx] =
            to_tf32(t[tx][ty + (j << 3)]);
}

// ---------------------------------------------------------------------------
// tf32 mma.sync GEMM, 3-stage cp.async, ldmatrix fragment feeds.
// A (pre-tf32) [.,C_] -> As [128][36]; W^T (pre-tf32) [n][C_] -> Bs [128][36].
// MODE 0: epilogue scatters q/k (as [b,h,t,d]) and v (as [b,h,d,t]), tf32,
//         q scaled by 0.125*log2e.  MODE 1: out (+bias) fp32.
// ---------------------------------------------------------------------------
#define BK       32
#define NCHUNK   (C_ / BK)    // 24
#define APITCH   36
#define MM_STAGE (2 * 128 * APITCH)             // 9216 floats
#define MM_SMEM  (3 * MM_STAGE * 4)             // 110592 bytes

template<int MODE>
__global__ __launch_bounds__(256, 2) void mm_mma_kernel(
    const float* __restrict__ A, const float* __restrict__ Wt,
    const float* __restrict__ bias, float* __restrict__ out, int Nw)
{
    extern __shared__ float sm[];
    const uint32_t sb = smem_u32(sm);

    const int tid  = threadIdx.x;
    const int wid  = tid >> 5;
    const int lane = tid & 31;
    const int g    = lane >> 2;
    const int tig  = lane & 3;
    const int sub  = lane >> 3;      // ldmatrix matrix index 0..3
    const int ro   = lane & 7;       // row within matrix

    const int bn = blockIdx.x << 7;
    const int bm = blockIdx.y << 7;
    const int wm = (wid >> 2) << 6;
    const int wn = (wid & 3) << 5;

    // ldmatrix lane base addresses (bytes)
    const uint32_t aBase = sb +
        (uint32_t)((wm + ((sub & 1) << 3) + ro) * APITCH + ((sub >> 1) << 2)) * 4;
    const uint32_t bBase = sb + (uint32_t)(128 * APITCH) * 4 +
        (uint32_t)((wn + ((sub >> 1) << 3) + ro) * APITCH + ((sub & 1) << 2)) * 4;

    auto issue = [&](int k0, int st) {
        const uint32_t bufA = st * MM_STAGE;
        const uint32_t bufB = bufA + 128 * APITCH;
        #pragma unroll
        for (int p = 0; p < 4; p++) {
            const int idx = tid + (p << 8);
            const int r   = idx >> 3;
            const int s4  = (idx & 7) << 2;
            cp16(sb + (uint32_t)(bufA + r * APITCH + s4) * 4,
                 A + (size_t)(bm + r) * C_ + k0 + s4);
        }
        #pragma unroll
        for (int p = 0; p < 4; p++) {
            const int idx = tid + (p << 8);
            const int r   = idx >> 3;
            const int s4  = (idx & 7) << 2;
            cp16(sb + (uint32_t)(bufB + r * APITCH + s4) * 4,
                 Wt + (size_t)(bn + r) * C_ + k0 + s4);
        }
        cp_commit();
    };

    float acc[4][4][4] = {};

    issue(0, 0);
    issue(BK, 1);

    int st = 0;
    for (int it = 0; it < NCHUNK; ++it) {
        if (it + 2 < NCHUNK) {
            issue((it + 2) << 5, (st + 2) % 3);
            cp_wait<2>();
        } else if (it + 1 < NCHUNK) {
            cp_wait<1>();
        } else {
            cp_wait<0>();
        }
        __syncthreads();

        const uint32_t stB = (uint32_t)(st * MM_STAGE) * 4;

        #pragma unroll
        for (int kkb = 0; kkb < 4; kkb++) {       // k-step of 8: col bytes = kkb*32
            uint32_t af[4][4], bfr[8];
            #pragma unroll
            for (int mt = 0; mt < 4; mt++)
                ldsm_x4(af[mt], aBase + stB + (uint32_t)(mt * 16 * APITCH * 4) + (kkb << 5));
            #pragma unroll
            for (int nb2 = 0; nb2 < 2; nb2++)
                ldsm_x4(&bfr[nb2 << 2], bBase + stB + (uint32_t)(nb2 * 16 * APITCH * 4) + (kkb << 5));
            #pragma unroll
            for (int mt = 0; mt < 4; mt++)
                #pragma unroll
                for (int nt = 0; nt < 4; nt++)
                    mma_16x8x8(acc[mt][nt], af[mt], &bfr[nt << 1]);
        }
        __syncthreads();
        st = (st + 1) % 3;
    }

    const float qscale = 0.125f * 1.44269504f;
    #pragma unroll
    for (int mt = 0; mt < 4; mt++) {
        #pragma unroll
        for (int half = 0; half < 2; half++) {
            const int row = wm + (mt << 4) + g + (half << 3);
            const int m   = bm + row;
            #pragma unroll
            for (int nt = 0; nt < 4; nt++) {
                const int col = wn + (nt << 3) + (tig << 1);
                const int n   = bn + col;
                float2 v;
                v.x = acc[mt][nt][half ? 2 : 0] + bias[n];
                v.y = acc[mt][nt][half ? 3 : 1] + bias[n + 1];
                if (MODE == 1) {
                    *reinterpret_cast<float2*>(out + (size_t)m * Nw + n) = v;
                } else {
                    const int which = bn / C_;
                    if (which == 0) { v.x *= qscale; v.y *= qscale; }
                    v.x = to_tf32(v.x); v.y = to_tf32(v.y);
                    const int c768 = n - which * C_;
                    const int h  = c768 >> 6;
                    const int d0 = c768 & 63;
                    const int bb = m >> 11;
                    const int t  = m & (T_ - 1);
                    if (which == 2) {   // v stored [b,h,d,t]
                        float* vb = g_v + (((size_t)bb * H_ + h) * DH_) * T_ + t;
                        vb[(size_t)d0 * T_]       = v.x;
                        vb[(size_t)(d0 + 1) * T_] = v.y;
                    } else {
                        float* dst = ((which == 0) ? g_q : g_k)
                                     + ((((size_t)bb * H_ + h) * T_ + t) << 6) + d0;
                        *reinterpret_cast<float2*>(dst) = v;
                    }
                }
            }
        }
    }
}

// ---------------------------------------------------------------------------
// Causal flash attention via mma.sync tf32 + ldmatrix feeds.
// 256 threads (8 warps), Q tile 128 (16 rows/warp), KV tile 64.
// Qs [q][68], Ks [kv][68], Vs [d][68] (V global is [b,h,d,t]), Ps [q][68].
// Inputs pre-tf32 (q pre-scaled by 0.125*log2e). 2 CTAs/SM.
// ---------------------------------------------------------------------------
#define QSP   68
#define KSP   68
#define VSP   68
#define PSP   68
#define QS_OFF 0
#define KS_OFF (128 * QSP)                    // 8704
#define VS_OFF (KS_OFF + 64 * KSP)            // 13056
#define PS_OFF (VS_OFF + 64 * VSP)            // 17408
#define ATTN_SMEM ((PS_OFF + 128 * PSP) * 4)  // 104448 bytes

__global__ __launch_bounds__(256, 2) void attn_mma_kernel()
{
    extern __shared__ float sm[];
    const uint32_t sb = smem_u32(sm);
    float* Ps = sm + PS_OFF;

    const int tid  = threadIdx.x;
    const int wid  = tid >> 5;
    const int lane = tid & 31;
    const int g    = lane >> 2;
    const int tig  = lane & 3;
    const int sub  = lane >> 3;
    const int ro   = lane & 7;

    const int qt    = (int)gridDim.x - 1 - (int)blockIdx.x;   // heavy first
    const int bh    = blockIdx.y;
    const int qbase = qt << 7;

    const float* Qg = g_q + (size_t)bh * T_ * DH_;
    const float* Kg = g_k + (size_t)bh * T_ * DH_;
    const float* Vg = g_v + (size_t)bh * DH_ * T_;   // [d][t]

    // ldmatrix lane base addresses (bytes)
    const uint32_t qBase = sb +
        (uint32_t)(QS_OFF + ((wid << 4) + ((sub & 1) << 3) + ro) * QSP + ((sub >> 1) << 2)) * 4;
    const uint32_t kBase = sb +
        (uint32_t)(KS_OFF + (((sub >> 1) << 3) + ro) * KSP + ((sub & 1) << 2)) * 4;
    const uint32_t vBase = sb +
        (uint32_t)(VS_OFF + (((sub >> 1) << 3) + ro) * VSP + ((sub & 1) << 2)) * 4;
    const uint32_t pBase = sb +
        (uint32_t)(PS_OFF + ((wid << 4) + ((sub & 1) << 3) + ro) * PSP + ((sub >> 1) << 2)) * 4;

    // Q tile via cp.async: 128 rows x 64 floats
    #pragma unroll
    for (int p = 0; p < 8; p++) {
        const int idx = tid + (p << 8);
        const int r   = idx >> 4;
        const int s4  = (idx & 15) << 2;
        cp16(sb + (uint32_t)(QS_OFF + r * QSP + s4) * 4,
             Qg + (size_t)(qbase + r) * DH_ + s4);
    }
    cp_commit();

    const int rq0  = (wid << 4) + g;
    const int row0 = qbase + rq0;
    const int row1 = row0 + 8;

    float m0 = -1e30f, m1 = -1e30f, l0 = 0.0f, l1 = 0.0f;
    float of[8][4] = {};

    const int ntiles = (qbase >> 6) + 2;

    cp_wait<0>();
    __syncthreads();

    for (int kt = 0; kt < ntiles; kt++) {
        const int kvb = kt << 6;
        __syncthreads();

        // K tile [kv][d] and V tile [d][kv] via cp.async
        #pragma unroll
        for (int p = 0; p < 4; p++) {
            const int idx = tid + (p << 8);
            const int r   = idx >> 4;
            const int s4  = (idx & 15) << 2;
            cp16(sb + (uint32_t)(KS_OFF + r * KSP + s4) * 4,
                 Kg + (size_t)(kvb + r) * DH_ + s4);
        }
        #pragma unroll
        for (int p = 0; p < 4; p++) {
            const int idx = tid + (p << 8);
            const int r   = idx >> 4;          // d
            const int s4  = (idx & 15) << 2;   // kv offset
            cp16(sb + (uint32_t)(VS_OFF + r * VSP + s4) * 4,
                 Vg + (size_t)r * T_ + kvb + s4);
        }
        cp_commit();
        cp_wait<0>();
        __syncthreads();

        // S = Q K^T
        float sf[8][4] = {};
        #pragma unroll
        for (int kk = 0; kk < 8; kk++) {
            uint32_t qa[4];
            ldsm_x4(qa, qBase + (kk << 5));
            #pragma unroll
            for (int nb2 = 0; nb2 < 4; nb2++) {
                uint32_t kb4[4];
                ldsm_x4(kb4, kBase + (uint32_t)(nb2 * 16 * KSP * 4) + (kk << 5));
                mma_16x8x8(sf[nb2 << 1], qa, kb4);
                mma_16x8x8(sf[(nb2 << 1) + 1], qa, kb4 + 2);
            }
        }

        // causal mask + row max
        float mt0 = -1e30f, mt1 = -1e30f;
        #pragma unroll
        for (int nt = 0; nt < 8; nt++) {
            const int col = kvb + (nt << 3) + (tig << 1);
            if (col > row0)     sf[nt][0] = -1e30f;
            if (col + 1 > row0) sf[nt][1] = -1e30f;
            if (col > row1)     sf[nt][2] = -1e30f;
            if (col + 1 > row1) sf[nt][3] = -1e30f;
            mt0 = fmaxf(mt0, fmaxf(sf[nt][0], sf[nt][1]));
            mt1 = fmaxf(mt1, fmaxf(sf[nt][2], sf[nt][3]));
        }
        mt0 = fmaxf(mt0, __shfl_xor_sync(0xffffffffu, mt0, 1));
        mt0 = fmaxf(mt0, __shfl_xor_sync(0xffffffffu, mt0, 2));
        mt1 = fmaxf(mt1, __shfl_xor_sync(0xffffffffu, mt1, 1));
        mt1 = fmaxf(mt1, __shfl_xor_sync(0xffffffffu, mt1, 2));

        const float m0n = fmaxf(m0, mt0);
        const float m1n = fmaxf(m1, mt1);
        const float corr0 = fexp2(m0 - m0n);
        const float corr1 = fexp2(m1 - m1n);
        m0 = m0n; m1 = m1n;

        // exponentiate, partial row sums, store P (tf32)
        float rs0 = 0.0f, rs1 = 0.0f;
        #pragma unroll
        for (int nt = 0; nt < 8; nt++) {
            const float p0 = fexp2(sf[nt][0] - m0);
            const float p1 = fexp2(sf[nt][1] - m0);
            const float p2 = fexp2(sf[nt][2] - m1);
            const float p3 = fexp2(sf[nt][3] - m1);
            rs0 += p0 + p1;
            rs1 += p2 + p3;
            float2 v01; v01.x = to_tf32(p0); v01.y = to_tf32(p1);
            float2 v23; v23.x = to_tf32(p2); v23.y = to_tf32(p3);
            *reinterpret_cast<float2*>(&Ps[rq0 * PSP + (nt << 3) + (tig << 1)]) = v01;
            *reinterpret_cast<float2*>(&Ps[(rq0 + 8) * PSP + (nt << 3) + (tig << 1)]) = v23;
        }
        l0 = l0 * corr0 + rs0;
        l1 = l1 * corr1 + rs1;

        #pragma unroll
        for (int nt = 0; nt < 8; nt++) {
            of[nt][0] *= corr0; of[nt][1] *= corr0;
            of[nt][2] *= corr1; of[nt][3] *= corr1;
        }
        __syncwarp();

        // O += P V   (A-frags from Ps, B-frags from Vs [d][kv])
        #pragma unroll
        for (int kk = 0; kk < 8; kk++) {
            uint32_t pa[4];
            ldsm_x4(pa, pBase + (kk << 5));
            #pragma unroll
            for (int nb2 = 0; nb2 < 4; nb2++) {
                uint32_t vb4[4];
                ldsm_x4(vb4, vBase + (uint32_t)(nb2 * 16 * VSP * 4) + (kk << 5));
                mma_16x8x8(of[nb2 << 1], pa, vb4);
                mma_16x8x8(of[(nb2 << 1) + 1], pa, vb4 + 2);
            }
        }
        __syncwarp();
    }

    l0 += __shfl_xor_sync(0xffffffffu, l0, 1);
    l0 += __shfl_xor_sync(0xffffffffu, l0, 2);
    l1 += __shfl_xor_sync(0xffffffffu, l1, 1);
    l1 += __shfl_xor_sync(0xffffffffu, l1, 2);
    const float inv0 = 1.0f / l0;
    const float inv1 = 1.0f / l1;

    const int b = bh / H_;
    const int h = bh - b * H_;
    float* y0 = g_y + ((size_t)b * T_ + row0) * C_ + h * DH_;
    float* y1 = g_y + ((size_t)b * T_ + row1) * C_ + h * DH_;
    #pragma unroll
    for (int nt = 0; nt < 8; nt++) {
        const int d = (nt << 3) + (tig << 1);
        float2 v0; v0.x = to_tf32(of[nt][0] * inv0); v0.y = to_tf32(of[nt][1] * inv0);
        float2 v1; v1.x = to_tf32(of[nt][2] * inv1); v1.y = to_tf32(of[nt][3] * inv1);
        *reinterpret_cast<float2*>(y0 + d) = v0;
        *reinterpret_cast<float2*>(y1 + d) = v1;
    }
}

// ---------------------------------------------------------------------------
// Launch
// ---------------------------------------------------------------------------
extern "C" void kernel_launch(void* const* d_in, const int* in_sizes, int n_in,
                              void* d_out, int out_size)
{
    const float* x      = (const float*)d_in[0];
    const float* w_attn = (const float*)d_in[1];
    const float* b_attn = (const float*)d_in[2];
    const float* w_proj = (const float*)d_in[3];
    const float* b_proj = (const float*)d_in[4];
    float* out = (float*)d_out;

    cudaFuncSetAttribute(mm_mma_kernel<0>,
                         cudaFuncAttributeMaxDynamicSharedMemorySize, MM_SMEM);
    cudaFuncSetAttribute(mm_mma_kernel<1>,
                         cudaFuncAttributeMaxDynamicSharedMemorySize, MM_SMEM);
    cudaFuncSetAttribute(attn_mma_kernel,
                         cudaFuncAttributeMaxDynamicSharedMemorySize, ATTN_SMEM);

    float *g_xt_p, *g_wat_p, *g_wpt_p, *g_y_p;
    cudaGetSymbolAddress((void**)&g_xt_p,  g_xt);
    cudaGetSymbolAddress((void**)&g_wat_p, g_wat);
    cudaGetSymbolAddress((void**)&g_wpt_p, g_wpt);
    cudaGetSymbolAddress((void**)&g_y_p,   g_y);

    cvt_kernel<<<(M_ * C_) / 1024, 256>>>(x, g_xt_p);
    cvt_t_kernel<<<dim3(NQKV_ / 32, C_ / 32), 256>>>(w_attn, g_wat_p, C_, NQKV_);
    cvt_t_kernel<<<dim3(C_ / 32, C_ / 32), 256>>>(w_proj, g_wpt_p, C_, C_);

    dim3 g1(NQKV_ / 128, M_ / 128);   // (18, 64)
    mm_mma_kernel<0><<<g1, 256, MM_SMEM>>>(g_xt_p, g_wat_p, b_attn, nullptr, NQKV_);

    dim3 g2(T_ / 128, B_ * H_);       // (16, 48)
    attn_mma_kernel<<<g2, 256, ATTN_SMEM>>>();

    dim3 g3(C_ / 128, M_ / 128);      // (6, 64)
    mm_mma_kernel<1><<<g3, 256, MM_SMEM>>>(g_y_p, g_wpt_p, b_proj, out, C_);
}

// round 9
// speedup vs baseline: 7.4953x; 1.5590x over previous
#include <cuda_runtime.h>
#include <cuda_fp16.h>
#include <cstdint>

// Problem constants
#define B_    4
#define T_    2048
#define C_    768
#define H_    12
#define DH_   64
#define M_    (B_ * T_)      // 8192 rows
#define NQKV_ (3 * C_)       // 2304

// Scratch (allocation-free rule: __device__ globals) — all half now
__device__ __half g_q[B_ * H_ * T_ * DH_];   // [b,h,t,d] (pre-scaled by 0.125*log2e)
__device__ __half g_k[B_ * H_ * T_ * DH_];   // [b,h,t,d]
__device__ __half g_v[B_ * H_ * DH_ * T_];   // [b,h,d,t]  (TRANSPOSED)
__device__ __half g_y[M_ * C_];              // attention output
__device__ __half g_xh[M_ * C_];             // x -> half
__device__ __half g_wat[NQKV_ * C_];         // w_attn^T half [n][k]
__device__ __half g_wpt[C_ * C_];            // w_proj^T half [n][k]

static __device__ __forceinline__ uint32_t smem_u32(const void* p) {
    uint32_t a;
    asm("{ .reg .u64 t; cvta.to.shared.u64 t, %1; cvt.u32.u64 %0, t; }"
        : "=r"(a) : "l"(p));
    return a;
}

static __device__ __forceinline__ void cp16(uint32_t saddr, const void* g) {
    asm volatile("cp.async.cg.shared.global [%0], [%1], 16;"
                 :: "r"(saddr), "l"(g) : "memory");
}
static __device__ __forceinline__ void cp_commit() {
    asm volatile("cp.async.commit_group;" ::: "memory");
}
template<int N>
static __device__ __forceinline__ void cp_wait() {
    asm volatile("cp.async.wait_group %0;" :: "n"(N) : "memory");
}

static __device__ __forceinline__ void ldsm_x4(uint32_t* r, uint32_t saddr) {
    asm volatile("ldmatrix.sync.aligned.m8n8.x4.shared.b16 {%0,%1,%2,%3}, [%4];"
                 : "=r"(r[0]), "=r"(r[1]), "=r"(r[2]), "=r"(r[3]) : "r"(saddr));
}

// fp16 MMA, fp32 accumulate: D[16x8] += A[16x16] B[16x8]
static __device__ __forceinline__ void mma_16x8x16(float* c, const uint32_t* a,
                                                   const uint32_t* b) {
    asm volatile(
        "mma.sync.aligned.m16n8k16.row.col.f32.f16.f16.f32 "
        "{%0,%1,%2,%3}, {%4,%5,%6,%7}, {%8,%9}, {%0,%1,%2,%3};"
        : "+f"(c[0]), "+f"(c[1]), "+f"(c[2]), "+f"(c[3])
        : "r"(a[0]), "r"(a[1]), "r"(a[2]), "r"(a[3]), "r"(b[0]), "r"(b[1]));
}

// Fast exp2 on the FMA pipe (degree-5 minimax on [0,1)).
static __device__ __forceinline__ float fexp2(float x) {
    x = fmaxf(x, -126.0f);
    float fi = floorf(x);
    float f = x - fi;
    float p = fmaf(f, 0.00187757f, 0.00898934f);
    p = fmaf(f, p, 0.05582995f);
    p = fmaf(f, p, 0.24015361f);
    p = fmaf(f, p, 0.69315308f);
    p = fmaf(f, p, 1.0f);
    return p * __int_as_float(((int)fi + 127) << 23);
}

// ---------------------------------------------------------------------------
// Pre-conversion kernels
// ---------------------------------------------------------------------------
__global__ __launch_bounds__(256) void cvt_h_kernel(const float* __restrict__ in,
                                                    __half* __restrict__ out)
{
    const int i = blockIdx.x * 256 + threadIdx.x;
    float4 v = reinterpret_cast<const float4*>(in)[i];
    __half2* o = reinterpret_cast<__half2*>(out) + (i << 1);
    o[0] = __floats2half2_rn(v.x, v.y);
    o[1] = __floats2half2_rn(v.z, v.w);
}

// in fp32 [K][N] -> out half [N][K]. grid (N/32, K/32), 256 threads.
__global__ __launch_bounds__(256) void cvt_t_kernel(const float* __restrict__ in,
                                                    __half* __restrict__ out,
                                                    int K, int N)
{
    __shared__ float t[32][33];
    const int tx = threadIdx.x & 31;
    const int ty = threadIdx.x >> 5;
    const int nb = blockIdx.x << 5;
    const int kb = blockIdx.y << 5;
    #pragma unroll
    for (int j = 0; j < 4; j++)
        t[ty + (j << 3)][tx] = in[(size_t)(kb + ty + (j << 3)) * N + nb + tx];
    __syncthreads();
    #pragma unroll
    for (int j = 0; j < 4; j++)
        out[(size_t)(nb + ty + (j << 3)) * K + kb + tx] =
            __float2half_rn(t[tx][ty + (j << 3)]);
}

// ---------------------------------------------------------------------------
// fp16 mma.sync GEMM, 3-stage cp.async, ldmatrix feeds. 128x128 tile, BK=32.
// A half [.,C_] -> As [128][40]h; W^T half [n][C_] -> Bs [128][40]h.
// MODE 0: epilogue scatters q/k ([b,h,t,d]) and v ([b,h,d,t]) as half,
//         q scaled by 0.125*log2e.  MODE 1: out (+bias) fp32.
// ---------------------------------------------------------------------------
#define BK       32
#define NCHUNK   (C_ / BK)                 // 24
#define APITCH   40                        // halves; 80B = 16*5 -> ldsm conflict-free
#define MM_STAGE (2 * 128 * APITCH * 2)    // 20480 bytes
#define MM_SMEM  (3 * MM_STAGE)            // 61440 bytes

template<int MODE>
__global__ __launch_bounds__(256, 2) void mm_mma_kernel(
    const __half* __restrict__ A, const __half* __restrict__ Wt,
    const float* __restrict__ bias, float* __restrict__ out, int Nw)
{
    extern __shared__ char smc[];
    const uint32_t sb = smem_u32(smc);

    const int tid  = threadIdx.x;
    const int wid  = tid >> 5;
    const int lane = tid & 31;
    const int g    = lane >> 2;
    const int tig  = lane & 3;
    const int sub  = lane >> 3;
    const int ro   = lane & 7;

    const int bn = blockIdx.x << 7;
    const int bm = blockIdx.y << 7;
    const int wm = (wid >> 2) << 6;
    const int wn = (wid & 3) << 5;

    // ldmatrix lane bases (bytes, relative to stage start)
    const uint32_t aRel = (uint32_t)((wm + ((sub & 1) << 3) + ro) * APITCH +
                                     ((sub >> 1) << 3)) * 2;
    const uint32_t bRel = (uint32_t)(128 * APITCH * 2) +
                          (uint32_t)((wn + ((sub >> 1) << 3) + ro) * APITCH +
                                     ((sub & 1) << 3)) * 2;

    auto issue = [&](int k0, int st) {
        const uint32_t bufA = sb + st * MM_STAGE;
        const uint32_t bufB = bufA + 128 * APITCH * 2;
        #pragma unroll
        for (int p = 0; p < 2; p++) {
            const int idx = tid + (p << 8);     // 0..511
            const int r   = idx >> 2;           // 0..127
            const int s8  = (idx & 3) << 3;     // half offset 0,8,16,24
            cp16(bufA + (uint32_t)(r * APITCH + s8) * 2,
                 A + (size_t)(bm + r) * C_ + k0 + s8);
        }
        #pragma unroll
        for (int p = 0; p < 2; p++) {
            const int idx = tid + (p << 8);
            const int r   = idx >> 2;
            const int s8  = (idx & 3) << 3;
            cp16(bufB + (uint32_t)(r * APITCH + s8) * 2,
                 Wt + (size_t)(bn + r) * C_ + k0 + s8);
        }
        cp_commit();
    };

    float acc[4][4][4] = {};

    issue(0, 0);
    issue(BK, 1);

    int st = 0;
    for (int it = 0; it < NCHUNK; ++it) {
        if (it + 2 < NCHUNK) {
            issue((it + 2) << 5, (st + 2) % 3);
            cp_wait<2>();
        } else if (it + 1 < NCHUNK) {
            cp_wait<1>();
        } else {
            cp_wait<0>();
        }
        __syncthreads();

        const uint32_t stB = sb + st * MM_STAGE;

        #pragma unroll
        for (int ks = 0; ks < 2; ks++) {          // k-step of 16 halves = 32B
            uint32_t af[4][4], bf[2][4];
            #pragma unroll
            for (int mt = 0; mt < 4; mt++)
                ldsm_x4(af[mt], stB + aRel + (uint32_t)(mt * 16 * APITCH * 2) + (ks << 5));
            #pragma unroll
            for (int nb = 0; nb < 2; nb++)
                ldsm_x4(bf[nb], stB + bRel + (uint32_t)(nb * 16 * APITCH * 2) + (ks << 5));
            #pragma unroll
            for (int mt = 0; mt < 4; mt++)
                #pragma unroll
                for (int nb = 0; nb < 2; nb++) {
                    mma_16x8x16(acc[mt][nb << 1], af[mt], &bf[nb][0]);
                    mma_16x8x16(acc[mt][(nb << 1) + 1], af[mt], &bf[nb][2]);
                }
        }
        __syncthreads();
        st = (st + 1) % 3;
    }

    const float qscale = 0.125f * 1.44269504f;
    #pragma unroll
    for (int mt = 0; mt < 4; mt++) {
        #pragma unroll
        for (int half_ = 0; half_ < 2; half_++) {
            const int row = wm + (mt << 4) + g + (half_ << 3);
            const int m   = bm + row;
            #pragma unroll
            for (int nt = 0; nt < 4; nt++) {
                const int col = wn + (nt << 3) + (tig << 1);
                const int n   = bn + col;
                float2 v;
                v.x = acc[mt][nt][half_ ? 2 : 0] + bias[n];
                v.y = acc[mt][nt][half_ ? 3 : 1] + bias[n + 1];
                if (MODE == 1) {
                    *reinterpret_cast<float2*>(out + (size_t)m * Nw + n) = v;
                } else {
                    const int which = bn / C_;
                    if (which == 0) { v.x *= qscale; v.y *= qscale; }
                    const int c768 = n - which * C_;
                    const int h  = c768 >> 6;
                    const int d0 = c768 & 63;
                    const int bb = m >> 11;
                    const int t  = m & (T_ - 1);
                    if (which == 2) {   // v stored [b,h,d,t]
                        __half* vb = g_v + (((size_t)bb * H_ + h) * DH_) * T_ + t;
                        vb[(size_t)d0 * T_]       = __float2half_rn(v.x);
                        vb[(size_t)(d0 + 1) * T_] = __float2half_rn(v.y);
                    } else {
                        __half* dst = ((which == 0) ? g_q : g_k)
                                      + ((((size_t)bb * H_ + h) * T_ + t) << 6) + d0;
                        *reinterpret_cast<__half2*>(dst) = __floats2half2_rn(v.x, v.y);
                    }
                }
            }
        }
    }
}

// ---------------------------------------------------------------------------
// Causal flash attention, fp16 mma + ldmatrix, double-buffered K/V.
// 256 threads (8 warps), Q tile 128 (16 rows/warp), KV tile 64.
// Qs [q][72]h, K/V stages {Ks [kv][72]h, Vs [d][72]h} x2, Ps [q][72]h.
// ---------------------------------------------------------------------------
#define ATP        72                          // halves; 144B = 16*9
#define QS_BYTES   (128 * ATP * 2)             // 18432
#define KV_K_BYTES (64 * ATP * 2)              // 9216
#define KV_STAGE   (2 * KV_K_BYTES)            // 18432 (K + V)
#define PS_OFF_B   (QS_BYTES + 2 * KV_STAGE)   // 55296
#define ATTN_SMEM  (PS_OFF_B + 128 * ATP * 2)  // 73728 bytes

__global__ __launch_bounds__(256, 2) void attn_mma_kernel()
{
    extern __shared__ char smc[];
    const uint32_t sb = smem_u32(smc);
    __half* Psh = reinterpret_cast<__half*>(smc + PS_OFF_B);

    const int tid  = threadIdx.x;
    const int wid  = tid >> 5;
    const int lane = tid & 31;
    const int g    = lane >> 2;
    const int tig  = lane & 3;
    const int sub  = lane >> 3;
    const int ro   = lane & 7;

    const int qt    = (int)gridDim.x - 1 - (int)blockIdx.x;   // heavy first
    const int bh    = blockIdx.y;
    const int qbase = qt << 7;

    const __half* Qg = g_q + (size_t)bh * T_ * DH_;
    const __half* Kg = g_k + (size_t)bh * T_ * DH_;
    const __half* Vg = g_v + (size_t)bh * DH_ * T_;   // [d][t]

    // ldmatrix lane bases (bytes)
    const uint32_t qB  = sb + (uint32_t)(((wid << 4) + ((sub & 1) << 3) + ro) * ATP +
                                         ((sub >> 1) << 3)) * 2;
    const uint32_t pB  = sb + PS_OFF_B +
                         (uint32_t)(((wid << 4) + ((sub & 1) << 3) + ro) * ATP +
                                    ((sub >> 1) << 3)) * 2;
    const uint32_t bRel = (uint32_t)(((((sub >> 1) << 3) + ro) * ATP +
                                      ((sub & 1) << 3)) * 2);

    // Q tile: 128 rows x 64 halves = 1024 x 16B, 4 per thread
    #pragma unroll
    for (int p = 0; p < 4; p++) {
        const int idx = tid + (p << 8);
        const int r   = idx >> 3;
        const int s8  = (idx & 7) << 3;
        cp16(sb + (uint32_t)(r * ATP + s8) * 2,
             Qg + (size_t)(qbase + r) * DH_ + s8);
    }
    // K/V tile issue: each 64 rows x 64 halves = 512 x 16B, 2 per thread
    auto issueKV = [&](int kvb, int stg) {
        const uint32_t kOff = sb + QS_BYTES + stg * KV_STAGE;
        const uint32_t vOff = kOff + KV_K_BYTES;
        #pragma unroll
        for (int p = 0; p < 2; p++) {
            const int idx = tid + (p << 8);
            const int r   = idx >> 3;
            const int s8  = (idx & 7) << 3;
            cp16(kOff + (uint32_t)(r * ATP + s8) * 2,
                 Kg + (size_t)(kvb + r) * DH_ + s8);
        }
        #pragma unroll
        for (int p = 0; p < 2; p++) {
            const int idx = tid + (p << 8);
            const int r   = idx >> 3;          // d
            const int s8  = (idx & 7) << 3;    // kv offset
            cp16(vOff + (uint32_t)(r * ATP + s8) * 2,
                 Vg + (size_t)r * T_ + kvb + s8);
        }
        cp_commit();
    };

    const int ntiles = (qbase >> 6) + 2;   // >= 2 always

    issueKV(0, 0);                          // group includes Q loads too
    issueKV(64, 1);                         // ntiles >= 2 guaranteed

    const int rq0  = (wid << 4) + g;
    const int row0 = qbase + rq0;
    const int row1 = row0 + 8;

    float m0 = -1e30f, m1 = -1e30f, l0 = 0.0f, l1 = 0.0f;
    float of[8][4] = {};

    for (int kt = 0; kt < ntiles; kt++) {
        const int kvb = kt << 6;
        if (kt + 1 < ntiles) cp_wait<1>(); else cp_wait<0>();
        __syncthreads();

        const uint32_t kSt = sb + QS_BYTES + (uint32_t)((kt & 1) * KV_STAGE);
        const uint32_t vSt = kSt + KV_K_BYTES;

        // S = Q K^T   (4 k-steps of 16 over d=64)
        float sf[8][4] = {};
        #pragma unroll
        for (int ks = 0; ks < 4; ks++) {
            uint32_t qa[4];
            ldsm_x4(qa, qB + (ks << 5));
            #pragma unroll
            for (int nb = 0; nb < 4; nb++) {
                uint32_t kb4[4];
                ldsm_x4(kb4, kSt + bRel + (uint32_t)(nb * 16 * ATP * 2) + (ks << 5));
                mma_16x8x16(sf[nb << 1], qa, kb4);
                mma_16x8x16(sf[(nb << 1) + 1], qa, kb4 + 2);
            }
        }

        // causal mask + row max
        float mt0 = -1e30f, mt1 = -1e30f;
        #pragma unroll
        for (int nt = 0; nt < 8; nt++) {
            const int col = kvb + (nt << 3) + (tig << 1);
            if (col > row0)     sf[nt][0] = -1e30f;
            if (col + 1 > row0) sf[nt][1] = -1e30f;
            if (col > row1)     sf[nt][2] = -1e30f;
            if (col + 1 > row1) sf[nt][3] = -1e30f;
            mt0 = fmaxf(mt0, fmaxf(sf[nt][0], sf[nt][1]));
            mt1 = fmaxf(mt1, fmaxf(sf[nt][2], sf[nt][3]));
        }
        mt0 = fmaxf(mt0, __shfl_xor_sync(0xffffffffu, mt0, 1));
        mt0 = fmaxf(mt0, __shfl_xor_sync(0xffffffffu, mt0, 2));
        mt1 = fmaxf(mt1, __shfl_xor_sync(0xffffffffu, mt1, 1));
        mt1 = fmaxf(mt1, __shfl_xor_sync(0xffffffffu, mt1, 2));

        const float m0n = fmaxf(m0, mt0);
        const float m1n = fmaxf(m1, mt1);
        const float corr0 = fexp2(m0 - m0n);
        const float corr1 = fexp2(m1 - m1n);
        m0 = m0n; m1 = m1n;

        // exponentiate, partial row sums, store P (half)
        float rs0 = 0.0f, rs1 = 0.0f;
        #pragma unroll
        for (int nt = 0; nt < 8; nt++) {
            const float p0 = fexp2(sf[nt][0] - m0);
            const float p1 = fexp2(sf[nt][1] - m0);
            const float p2 = fexp2(sf[nt][2] - m1);
            const float p3 = fexp2(sf[nt][3] - m1);
            rs0 += p0 + p1;
            rs1 += p2 + p3;
            *reinterpret_cast<__half2*>(&Psh[rq0 * ATP + (nt << 3) + (tig << 1)]) =
                __floats2half2_rn(p0, p1);
            *reinterpret_cast<__half2*>(&Psh[(rq0 + 8) * ATP + (nt << 3) + (tig << 1)]) =
                __floats2half2_rn(p2, p3);
        }
        l0 = l0 * corr0 + rs0;
        l1 = l1 * corr1 + rs1;

        #pragma unroll
        for (int nt = 0; nt < 8; nt++) {
            of[nt][0] *= corr0; of[nt][1] *= corr0;
            of[nt][2] *= corr1; of[nt][3] *= corr1;
        }
        __syncwarp();

        // O += P V   (4 k-steps of 16 over kv=64)
        #pragma unroll
        for (int ks = 0; ks < 4; ks++) {
            uint32_t pa[4];
            ldsm_x4(pa, pB + (ks << 5));
            #pragma unroll
            for (int nb = 0; nb < 4; nb++) {
                uint32_t vb4[4];
                ldsm_x4(vb4, vSt + bRel + (uint32_t)(nb * 16 * ATP * 2) + (ks << 5));
                mma_16x8x16(of[nb << 1], pa, vb4);
                mma_16x8x16(of[(nb << 1) + 1], pa, vb4 + 2);
            }
        }
        __syncthreads();                       // all warps done with stage kt&1
        if (kt + 2 < ntiles) issueKV((kt + 2) << 6, kt & 1);
    }

    l0 += __shfl_xor_sync(0xffffffffu, l0, 1);
    l0 += __shfl_xor_sync(0xffffffffu, l0, 2);
    l1 += __shfl_xor_sync(0xffffffffu, l1, 1);
    l1 += __shfl_xor_sync(0xffffffffu, l1, 2);
    const float inv0 = 1.0f / l0;
    const float inv1 = 1.0f / l1;

    const int b = bh / H_;
    const int h = bh - b * H_;
    __half* y0 = g_y + ((size_t)b * T_ + row0) * C_ + h * DH_;
    __half* y1 = g_y + ((size_t)b * T_ + row1) * C_ + h * DH_;
    #pragma unroll
    for (int nt = 0; nt < 8; nt++) {
        const int d = (nt << 3) + (tig << 1);
        *reinterpret_cast<__half2*>(y0 + d) =
            __floats2half2_rn(of[nt][0] * inv0, of[nt][1] * inv0);
        *reinterpret_cast<__half2*>(y1 + d) =
            __floats2half2_rn(of[nt][2] * inv1, of[nt][3] * inv1);
    }
}

// ---------------------------------------------------------------------------
// Launch
// ---------------------------------------------------------------------------
extern "C" void kernel_launch(void* const* d_in, const int* in_sizes, int n_in,
                              void* d_out, int out_size)
{
    const float* x      = (const float*)d_in[0];
    const float* w_attn = (const float*)d_in[1];
    const float* b_attn = (const float*)d_in[2];
    const float* w_proj = (const float*)d_in[3];
    const float* b_proj = (const float*)d_in[4];
    float* out = (float*)d_out;

    cudaFuncSetAttribute(mm_mma_kernel<0>,
                         cudaFuncAttributeMaxDynamicSharedMemorySize, MM_SMEM);
    cudaFuncSetAttribute(mm_mma_kernel<1>,
                         cudaFuncAttributeMaxDynamicSharedMemorySize, MM_SMEM);
    cudaFuncSetAttribute(attn_mma_kernel,
                         cudaFuncAttributeMaxDynamicSharedMemorySize, ATTN_SMEM);

    __half *g_xh_p, *g_wat_p, *g_wpt_p, *g_y_p;
    cudaGetSymbolAddress((void**)&g_xh_p,  g_xh);
    cudaGetSymbolAddress((void**)&g_wat_p, g_wat);
    cudaGetSymbolAddress((void**)&g_wpt_p, g_wpt);
    cudaGetSymbolAddress((void**)&g_y_p,   g_y);

    cvt_h_kernel<<<(M_ * C_) / 1024, 256>>>(x, g_xh_p);
    cvt_t_kernel<<<dim3(NQKV_ / 32, C_ / 32), 256>>>(w_attn, g_wat_p, C_, NQKV_);
    cvt_t_kernel<<<dim3(C_ / 32, C_ / 32), 256>>>(w_proj, g_wpt_p, C_, C_);

    dim3 g1(NQKV_ / 128, M_ / 128);   // (18, 64)
    mm_mma_kernel<0><<<g1, 256, MM_SMEM>>>(g_xh_p, g_wat_p, b_attn, nullptr, NQKV_);

    dim3 g2(T_ / 128, B_ * H_);       // (16, 48)
    attn_mma_kernel<<<g2, 256, ATTN_SMEM>>>();

    dim3 g3(C_ / 128, M_ / 128);      // (6, 64)
    mm_mma_kernel<1><<<g3, 256, MM_SMEM>>>(g_y_p, g_wpt_p, b_proj, out, C_);
}

// round 10
// speedup vs baseline: 8.3463x; 1.1135x over previous
#include <cuda_runtime.h>
#include <cuda_fp16.h>
#include <cstdint>

// Problem constants
#define B_    4
#define T_    2048
#define C_    768
#define H_    12
#define DH_   64
#define M_    (B_ * T_)      // 8192 rows
#define NQKV_ (3 * C_)       // 2304

// Scratch (allocation-free rule: __device__ globals) — all half
__device__ __half g_q[B_ * H_ * T_ * DH_];   // [b,h,t,d] (pre-scaled by 0.125*log2e)
__device__ __half g_k[B_ * H_ * T_ * DH_];   // [b,h,t,d]
__device__ __half g_v[B_ * H_ * DH_ * T_];   // [b,h,d,t]  (TRANSPOSED)
__device__ __half g_y[M_ * C_];              // attention output
__device__ __half g_xh[M_ * C_];             // x -> half
__device__ __half g_wat[NQKV_ * C_];         // w_attn^T half [n][k]
__device__ __half g_wpt[C_ * C_];            // w_proj^T half [n][k]

static __device__ __forceinline__ uint32_t smem_u32(const void* p) {
    uint32_t a;
    asm("{ .reg .u64 t; cvta.to.shared.u64 t, %1; cvt.u32.u64 %0, t; }"
        : "=r"(a) : "l"(p));
    return a;
}

static __device__ __forceinline__ void cp16(uint32_t saddr, const void* g) {
    asm volatile("cp.async.cg.shared.global [%0], [%1], 16;"
                 :: "r"(saddr), "l"(g) : "memory");
}
static __device__ __forceinline__ void cp_commit() {
    asm volatile("cp.async.commit_group;" ::: "memory");
}
template<int N>
static __device__ __forceinline__ void cp_wait() {
    asm volatile("cp.async.wait_group %0;" :: "n"(N) : "memory");
}

static __device__ __forceinline__ void ldsm_x4(uint32_t* r, uint32_t saddr) {
    asm volatile("ldmatrix.sync.aligned.m8n8.x4.shared.b16 {%0,%1,%2,%3}, [%4];"
                 : "=r"(r[0]), "=r"(r[1]), "=r"(r[2]), "=r"(r[3]) : "r"(saddr));
}

// fp16 MMA, fp32 accumulate: D[16x8] += A[16x16] B[16x8]
static __device__ __forceinline__ void mma_16x8x16(float* c, const uint32_t* a,
                                                   const uint32_t* b) {
    asm volatile(
        "mma.sync.aligned.m16n8k16.row.col.f32.f16.f16.f32 "
        "{%0,%1,%2,%3}, {%4,%5,%6,%7}, {%8,%9}, {%0,%1,%2,%3};"
        : "+f"(c[0]), "+f"(c[1]), "+f"(c[2]), "+f"(c[3])
        : "r"(a[0]), "r"(a[1]), "r"(a[2]), "r"(a[3]), "r"(b[0]), "r"(b[1]));
}

// Fast exp2 on the FMA pipe (degree-5 minimax on [0,1)).
static __device__ __forceinline__ float fexp2(float x) {
    x = fmaxf(x, -126.0f);
    float fi = floorf(x);
    float f = x - fi;
    float p = fmaf(f, 0.00187757f, 0.00898934f);
    p = fmaf(f, p, 0.05582995f);
    p = fmaf(f, p, 0.24015361f);
    p = fmaf(f, p, 0.69315308f);
    p = fmaf(f, p, 1.0f);
    return p * __int_as_float(((int)fi + 127) << 23);
}

// ---------------------------------------------------------------------------
// Pre-conversion kernels
// ---------------------------------------------------------------------------
__global__ __launch_bounds__(256) void cvt_h_kernel(const float* __restrict__ in,
                                                    __half* __restrict__ out)
{
    const int i = blockIdx.x * 256 + threadIdx.x;
    float4 v = reinterpret_cast<const float4*>(in)[i];
    __half2* o = reinterpret_cast<__half2*>(out) + (i << 1);
    o[0] = __floats2half2_rn(v.x, v.y);
    o[1] = __floats2half2_rn(v.z, v.w);
}

// in fp32 [K][N] -> out half [N][K]. grid (N/32, K/32), 256 threads.
__global__ __launch_bounds__(256) void cvt_t_kernel(const float* __restrict__ in,
                                                    __half* __restrict__ out,
                                                    int K, int N)
{
    __shared__ float t[32][33];
    const int tx = threadIdx.x & 31;
    const int ty = threadIdx.x >> 5;
    const int nb = blockIdx.x << 5;
    const int kb = blockIdx.y << 5;
    #pragma unroll
    for (int j = 0; j < 4; j++)
        t[ty + (j << 3)][tx] = in[(size_t)(kb + ty + (j << 3)) * N + nb + tx];
    __syncthreads();
    #pragma unroll
    for (int j = 0; j < 4; j++)
        out[(size_t)(nb + ty + (j << 3)) * K + kb + tx] =
            __float2half_rn(t[tx][ty + (j << 3)]);
}

// ---------------------------------------------------------------------------
// fp16 mma.sync GEMM, 3-stage cp.async (single sync/stage), ldmatrix feeds.
// 128x128 tile, BK=32.
// MODE 0: epilogue scatters q/k ([b,h,t,d]) and v ([b,h,d,t]) as half,
//         q scaled by 0.125*log2e.  MODE 1: out (+bias) fp32.
// ---------------------------------------------------------------------------
#define BK       32
#define NCHUNK   (C_ / BK)                 // 24
#define APITCH   40                        // halves; 80B
#define MM_STAGE (2 * 128 * APITCH * 2)    // 20480 bytes
#define MM_SMEM  (3 * MM_STAGE)            // 61440 bytes

template<int MODE>
__global__ __launch_bounds__(256, 2) void mm_mma_kernel(
    const __half* __restrict__ A, const __half* __restrict__ Wt,
    const float* __restrict__ bias, float* __restrict__ out, int Nw)
{
    extern __shared__ char smc[];
    const uint32_t sb = smem_u32(smc);

    const int tid  = threadIdx.x;
    const int wid  = tid >> 5;
    const int lane = tid & 31;
    const int g    = lane >> 2;
    const int tig  = lane & 3;
    const int sub  = lane >> 3;
    const int ro   = lane & 7;

    const int bn = blockIdx.x << 7;
    const int bm = blockIdx.y << 7;
    const int wm = (wid >> 2) << 6;
    const int wn = (wid & 3) << 5;

    const uint32_t aRel = (uint32_t)((wm + ((sub & 1) << 3) + ro) * APITCH +
                                     ((sub >> 1) << 3)) * 2;
    const uint32_t bRel = (uint32_t)(128 * APITCH * 2) +
                          (uint32_t)((wn + ((sub >> 1) << 3) + ro) * APITCH +
                                     ((sub & 1) << 3)) * 2;

    auto issue = [&](int k0, int st) {
        const uint32_t bufA = sb + st * MM_STAGE;
        const uint32_t bufB = bufA + 128 * APITCH * 2;
        #pragma unroll
        for (int p = 0; p < 2; p++) {
            const int idx = tid + (p << 8);
            const int r   = idx >> 2;
            const int s8  = (idx & 3) << 3;
            cp16(bufA + (uint32_t)(r * APITCH + s8) * 2,
                 A + (size_t)(bm + r) * C_ + k0 + s8);
        }
        #pragma unroll
        for (int p = 0; p < 2; p++) {
            const int idx = tid + (p << 8);
            const int r   = idx >> 2;
            const int s8  = (idx & 3) << 3;
            cp16(bufB + (uint32_t)(r * APITCH + s8) * 2,
                 Wt + (size_t)(bn + r) * C_ + k0 + s8);
        }
        cp_commit();
    };

    float acc[4][4][4] = {};

    issue(0, 0);
    issue(BK, 1);

    for (int it = 0; it < NCHUNK; ++it) {
        if (it + 1 < NCHUNK) cp_wait<1>(); else cp_wait<0>();
        __syncthreads();

        const uint32_t stB = sb + (it % 3) * MM_STAGE;

        #pragma unroll
        for (int ks = 0; ks < 2; ks++) {
            uint32_t af[4][4], bf[2][4];
            #pragma unroll
            for (int mt = 0; mt < 4; mt++)
                ldsm_x4(af[mt], stB + aRel + (uint32_t)(mt * 16 * APITCH * 2) + (ks << 5));
            #pragma unroll
            for (int nb = 0; nb < 2; nb++)
                ldsm_x4(bf[nb], stB + bRel + (uint32_t)(nb * 16 * APITCH * 2) + (ks << 5));
            #pragma unroll
            for (int mt = 0; mt < 4; mt++)
                #pragma unroll
                for (int nb = 0; nb < 2; nb++) {
                    mma_16x8x16(acc[mt][nb << 1], af[mt], &bf[nb][0]);
                    mma_16x8x16(acc[mt][(nb << 1) + 1], af[mt], &bf[nb][2]);
                }
        }
        if (it + 2 < NCHUNK) issue((it + 2) << 5, (it + 2) % 3);
    }

    const float qscale = 0.125f * 1.44269504f;
    #pragma unroll
    for (int mt = 0; mt < 4; mt++) {
        #pragma unroll
        for (int half_ = 0; half_ < 2; half_++) {
            const int row = wm + (mt << 4) + g + (half_ << 3);
            const int m   = bm + row;
            #pragma unroll
            for (int nt = 0; nt < 4; nt++) {
                const int col = wn + (nt << 3) + (tig << 1);
                const int n   = bn + col;
                float2 v;
                v.x = acc[mt][nt][half_ ? 2 : 0] + bias[n];
                v.y = acc[mt][nt][half_ ? 3 : 1] + bias[n + 1];
                if (MODE == 1) {
                    *reinterpret_cast<float2*>(out + (size_t)m * Nw + n) = v;
                } else {
                    const int which = bn / C_;
                    if (which == 0) { v.x *= qscale; v.y *= qscale; }
                    const int c768 = n - which * C_;
                    const int h  = c768 >> 6;
                    const int d0 = c768 & 63;
                    const int bb = m >> 11;
                    const int t  = m & (T_ - 1);
                    if (which == 2) {   // v stored [b,h,d,t]
                        __half* vb = g_v + (((size_t)bb * H_ + h) * DH_) * T_ + t;
                        vb[(size_t)d0 * T_]       = __float2half_rn(v.x);
                        vb[(size_t)(d0 + 1) * T_] = __float2half_rn(v.y);
                    } else {
                        __half* dst = ((which == 0) ? g_q : g_k)
                                      + ((((size_t)bb * H_ + h) * T_ + t) << 6) + d0;
                        *reinterpret_cast<__half2*>(dst) = __floats2half2_rn(v.x, v.y);
                    }
                }
            }
        }
    }
}

// ---------------------------------------------------------------------------
// Causal flash attention, fp16 mma + ldmatrix, 3-stage K/V pipeline.
// P stays in REGISTERS: fp16 C-fragment of S == A-fragment of PV (FA-2 trick).
// 256 threads (8 warps), Q tile 128 (16 rows/warp), KV tile 64. 2 CTAs/SM.
// ---------------------------------------------------------------------------
#define ATP        72                          // halves; 144B
#define QS_BYTES   (128 * ATP * 2)             // 18432
#define KV_K_BYTES (64 * ATP * 2)              // 9216
#define KV_STAGE   (2 * KV_K_BYTES)            // 18432 (K + V)
#define ATTN_SMEM  (QS_BYTES + 3 * KV_STAGE)   // 73728 bytes

__global__ __launch_bounds__(256, 2) void attn_mma_kernel()
{
    extern __shared__ char smc[];
    const uint32_t sb = smem_u32(smc);

    const int tid  = threadIdx.x;
    const int wid  = tid >> 5;
    const int lane = tid & 31;
    const int g    = lane >> 2;
    const int tig  = lane & 3;
    const int sub  = lane >> 3;
    const int ro   = lane & 7;

    const int qt    = (int)gridDim.x - 1 - (int)blockIdx.x;   // heavy first
    const int bh    = blockIdx.y;
    const int qbase = qt << 7;

    const __half* Qg = g_q + (size_t)bh * T_ * DH_;
    const __half* Kg = g_k + (size_t)bh * T_ * DH_;
    const __half* Vg = g_v + (size_t)bh * DH_ * T_;   // [d][t]

    const uint32_t qB = sb + (uint32_t)(((wid << 4) + ((sub & 1) << 3) + ro) * ATP +
                                        ((sub >> 1) << 3)) * 2;
    const uint32_t bRel = (uint32_t)(((((sub >> 1) << 3) + ro) * ATP +
                                      ((sub & 1) << 3)) * 2);

    // Q tile: 128 rows x 64 halves = 1024 x 16B, 4 per thread (joins group 0)
    #pragma unroll
    for (int p = 0; p < 4; p++) {
        const int idx = tid + (p << 8);
        const int r   = idx >> 3;
        const int s8  = (idx & 7) << 3;
        cp16(sb + (uint32_t)(r * ATP + s8) * 2,
             Qg + (size_t)(qbase + r) * DH_ + s8);
    }
    auto issueKV = [&](int kvb, int stg) {
        const uint32_t kOff = sb + QS_BYTES + stg * KV_STAGE;
        const uint32_t vOff = kOff + KV_K_BYTES;
        #pragma unroll
        for (int p = 0; p < 2; p++) {
            const int idx = tid + (p << 8);
            const int r   = idx >> 3;
            const int s8  = (idx & 7) << 3;
            cp16(kOff + (uint32_t)(r * ATP + s8) * 2,
                 Kg + (size_t)(kvb + r) * DH_ + s8);
        }
        #pragma unroll
        for (int p = 0; p < 2; p++) {
            const int idx = tid + (p << 8);
            const int r   = idx >> 3;          // d
            const int s8  = (idx & 7) << 3;    // kv offset
            cp16(vOff + (uint32_t)(r * ATP + s8) * 2,
                 Vg + (size_t)r * T_ + kvb + s8);
        }
        cp_commit();
    };

    const int ntiles = (qbase >> 6) + 2;   // >= 2 always

    issueKV(0, 0);                          // Q rides in this group
    issueKV(64, 1);

    const int rq0  = (wid << 4) + g;
    const int row0 = qbase + rq0;
    const int row1 = row0 + 8;

    float m0 = -1e30f, m1 = -1e30f, l0 = 0.0f, l1 = 0.0f;
    float of[8][4] = {};

    for (int kt = 0; kt < ntiles; kt++) {
        const int kvb = kt << 6;
        if (kt + 1 < ntiles) cp_wait<1>(); else cp_wait<0>();
        __syncthreads();

        const uint32_t kSt = sb + QS_BYTES + (uint32_t)((kt % 3) * KV_STAGE);
        const uint32_t vSt = kSt + KV_K_BYTES;

        // S = Q K^T   (4 k-steps of 16 over d=64)
        float sf[8][4] = {};
        #pragma unroll
        for (int ks = 0; ks < 4; ks++) {
            uint32_t qa[4];
            ldsm_x4(qa, qB + (ks << 5));
            #pragma unroll
            for (int nb = 0; nb < 4; nb++) {
                uint32_t kb4[4];
                ldsm_x4(kb4, kSt + bRel + (uint32_t)(nb * 16 * ATP * 2) + (ks << 5));
                mma_16x8x16(sf[nb << 1], qa, kb4);
                mma_16x8x16(sf[(nb << 1) + 1], qa, kb4 + 2);
            }
        }

        // causal mask + row max
        float mt0 = -1e30f, mt1 = -1e30f;
        #pragma unroll
        for (int nt = 0; nt < 8; nt++) {
            const int col = kvb + (nt << 3) + (tig << 1);
            if (col > row0)     sf[nt][0] = -1e30f;
            if (col + 1 > row0) sf[nt][1] = -1e30f;
            if (col > row1)     sf[nt][2] = -1e30f;
            if (col + 1 > row1) sf[nt][3] = -1e30f;
            mt0 = fmaxf(mt0, fmaxf(sf[nt][0], sf[nt][1]));
            mt1 = fmaxf(mt1, fmaxf(sf[nt][2], sf[nt][3]));
        }
        mt0 = fmaxf(mt0, __shfl_xor_sync(0xffffffffu, mt0, 1));
        mt0 = fmaxf(mt0, __shfl_xor_sync(0xffffffffu, mt0, 2));
        mt1 = fmaxf(mt1, __shfl_xor_sync(0xffffffffu, mt1, 1));
        mt1 = fmaxf(mt1, __shfl_xor_sync(0xffffffffu, mt1, 2));

        const float m0n = fmaxf(m0, mt0);
        const float m1n = fmaxf(m1, mt1);
        const float corr0 = fexp2(m0 - m0n);
        const float corr1 = fexp2(m1 - m1n);
        m0 = m0n; m1 = m1n;

        // exponentiate -> P packed directly as A-fragments (no smem!)
        uint32_t plo[8], phi[8];
        float rs0 = 0.0f, rs1 = 0.0f;
        #pragma unroll
        for (int nt = 0; nt < 8; nt++) {
            const float p0 = fexp2(sf[nt][0] - m0);
            const float p1 = fexp2(sf[nt][1] - m0);
            const float p2 = fexp2(sf[nt][2] - m1);
            const float p3 = fexp2(sf[nt][3] - m1);
            rs0 += p0 + p1;
            rs1 += p2 + p3;
            __half2 h01 = __floats2half2_rn(p0, p1);
            __half2 h23 = __floats2half2_rn(p2, p3);
            plo[nt] = *reinterpret_cast<uint32_t*>(&h01);
            phi[nt] = *reinterpret_cast<uint32_t*>(&h23);
        }
        l0 = l0 * corr0 + rs0;
        l1 = l1 * corr1 + rs1;

        #pragma unroll
        for (int nt = 0; nt < 8; nt++) {
            of[nt][0] *= corr0; of[nt][1] *= corr0;
            of[nt][2] *= corr1; of[nt][3] *= corr1;
        }

        // O += P V   (A-frags from registers, B-frags from Vs [d][kv])
        #pragma unroll
        for (int c = 0; c < 4; c++) {
            uint32_t pa[4];
            pa[0] = plo[c << 1];
            pa[1] = phi[c << 1];
            pa[2] = plo[(c << 1) + 1];
            pa[3] = phi[(c << 1) + 1];
            #pragma unroll
            for (int nb = 0; nb < 4; nb++) {
                uint32_t vb4[4];
                ldsm_x4(vb4, vSt + bRel + (uint32_t)(nb * 16 * ATP * 2) + (c << 5));
                mma_16x8x16(of[nb << 1], pa, vb4);
                mma_16x8x16(of[(nb << 1) + 1], pa, vb4 + 2);
            }
        }

        if (kt + 2 < ntiles) issueKV((kt + 2) << 6, (kt + 2) % 3);
    }

    l0 += __shfl_xor_sync(0xffffffffu, l0, 1);
    l0 += __shfl_xor_sync(0xffffffffu, l0, 2);
    l1 += __shfl_xor_sync(0xffffffffu, l1, 1);
    l1 += __shfl_xor_sync(0xffffffffu, l1, 2);
    const float inv0 = 1.0f / l0;
    const float inv1 = 1.0f / l1;

    const int b = bh / H_;
    const int h = bh - b * H_;
    __half* y0 = g_y + ((size_t)b * T_ + row0) * C_ + h * DH_;
    __half* y1 = g_y + ((size_t)b * T_ + row1) * C_ + h * DH_;
    #pragma unroll
    for (int nt = 0; nt < 8; nt++) {
        const int d = (nt << 3) + (tig << 1);
        *reinterpret_cast<__half2*>(y0 + d) =
            __floats2half2_rn(of[nt][0] * inv0, of[nt][1] * inv0);
        *reinterpret_cast<__half2*>(y1 + d) =
            __floats2half2_rn(of[nt][2] * inv1, of[nt][3] * inv1);
    }
}

// ---------------------------------------------------------------------------
// Launch
// ---------------------------------------------------------------------------
extern "C" void kernel_launch(void* const* d_in, const int* in_sizes, int n_in,
                              void* d_out, int out_size)
{
    const float* x      = (const float*)d_in[0];
    const float* w_attn = (const float*)d_in[1];
    const float* b_attn = (const float*)d_in[2];
    const float* w_proj = (const float*)d_in[3];
    const float* b_proj = (const float*)d_in[4];
    float* out = (float*)d_out;

    cudaFuncSetAttribute(mm_mma_kernel<0>,
                         cudaFuncAttributeMaxDynamicSharedMemorySize, MM_SMEM);
    cudaFuncSetAttribute(mm_mma_kernel<1>,
                         cudaFuncAttributeMaxDynamicSharedMemorySize, MM_SMEM);
    cudaFuncSetAttribute(attn_mma_kernel,
                         cudaFuncAttributeMaxDynamicSharedMemorySize, ATTN_SMEM);

    __half *g_xh_p, *g_wat_p, *g_wpt_p, *g_y_p;
    cudaGetSymbolAddress((void**)&g_xh_p,  g_xh);
    cudaGetSymbolAddress((void**)&g_wat_p, g_wat);
    cudaGetSymbolAddress((void**)&g_wpt_p, g_wpt);
    cudaGetSymbolAddress((void**)&g_y_p,   g_y);

    cvt_h_kernel<<<(M_ * C_) / 1024, 256>>>(x, g_xh_p);
    cvt_t_kernel<<<dim3(NQKV_ / 32, C_ / 32), 256>>>(w_attn, g_wat_p, C_, NQKV_);
    cvt_t_kernel<<<dim3(C_ / 32, C_ / 32), 256>>>(w_proj, g_wpt_p, C_, C_);

    dim3 g1(NQKV_ / 128, M_ / 128);   // (18, 64)
    mm_mma_kernel<0><<<g1, 256, MM_SMEM>>>(g_xh_p, g_wat_p, b_attn, nullptr, NQKV_);

    dim3 g2(T_ / 128, B_ * H_);       // (16, 48)
    attn_mma_kernel<<<g2, 256, ATTN_SMEM>>>();

    dim3 g3(C_ / 128, M_ / 128);      // (6, 64)
    mm_mma_kernel<1><<<g3, 256, MM_SMEM>>>(g_y_p, g_wpt_p, b_proj, out, C_);
}